// round 6
// baseline (speedup 1.0000x reference)
#include <cuda_runtime.h>
#include <cstdint>

#define B_  4
#define T_  2048
#define C_  1024
#define H_  128
#define BT_ (B_ * T_)
#define NUNITS 320   // split-K attention work units: 4 batches * 80

// Static device scratch (allocation-free). g_Q/K/V hold tf32-rounded values.
__device__ float g_Q[BT_ * H_];
__device__ float g_K[BT_ * H_];
__device__ float g_V[BT_ * H_];
__device__ float g_Opart[NUNITS * 64 * H_];  // unnormalized partial O
__device__ float g_ml[NUNITS * 64 * 2];      // per-row (m, l)

// ---------------------------------------------------------------------------
// Helpers
// ---------------------------------------------------------------------------
__device__ __forceinline__ float to_tf32(float x) {
    float r; asm("cvt.rna.tf32.f32 %0, %1;" : "=f"(r) : "f"(x)); return r;
}
__device__ __forceinline__ uint32_t fu(float x) { return __float_as_uint(x); }

__device__ __forceinline__ void mma_tf32(float* d, const uint32_t* a,
                                         uint32_t b0, uint32_t b1) {
    asm volatile(
        "mma.sync.aligned.m16n8k8.row.col.f32.tf32.tf32.f32 "
        "{%0,%1,%2,%3}, {%4,%5,%6,%7}, {%8,%9}, {%0,%1,%2,%3};"
        : "+f"(d[0]), "+f"(d[1]), "+f"(d[2]), "+f"(d[3])
        : "r"(a[0]), "r"(a[1]), "r"(a[2]), "r"(a[3]), "r"(b0), "r"(b1));
}
__device__ __forceinline__ uint32_t smem_u32(const void* p) {
    uint32_t a;
    asm("{ .reg .u64 t; cvta.to.shared.u64 t, %1; cvt.u32.u64 %0, t; }"
        : "=r"(a) : "l"(p));
    return a;
}

#define CP16(dst, src) \
    asm volatile("cp.async.cg.shared.global [%0], [%1], 16;" \
                 :: "r"(dst), "l"(src) : "memory")
#define CPCOMMIT() asm volatile("cp.async.commit_group;" ::: "memory")
#define CPWAIT(n)  asm volatile("cp.async.wait_group %0;" :: "n"(n) : "memory")

// XOR-swizzled row-major layouts (conflict-free frag reads, no padding)
__device__ __forceinline__ int swz128(int r, int c) {
    return r * 128 + (c ^ ((r & 7) << 2));
}
__device__ __forceinline__ int swz64(int r, int c) {
    return r * 64 + (c ^ ((r & 7) << 2));
}

// ---------------------------------------------------------------------------
// Kernel 1: fused QKV projection, TF32 mma.sync, double-buffered smem.
// CTA: 64(M) x 384(N = Q|K|V), K-slab 32, 512 thr = 16 warps (4M x 4N).
// Warp tile 16x96 (12 n-tiles). Slot-interleaved smem: fragment pair
// (k, k+4) adjacent -> one LDS.64 per fragment.
//   A: [kkb][sp][68 m][2]  (2176 fl)   B: [kkb][sp][388 n][2] (12416 fl)
// Outputs stored tf32-rounded (moves attention's cvt here).
// ---------------------------------------------------------------------------
#define PJ_A     2176
#define PJ_STAGE (2176 + 12416)          // 14592 floats
#define PJ_SMEM  (2 * PJ_STAGE * 4)      // 116736 B

__global__ __launch_bounds__(512, 1) void proj_mma(
    const float* __restrict__ x,
    const float* __restrict__ Wq,
    const float* __restrict__ Wk,
    const float* __restrict__ Wv)
{
    extern __shared__ float sm[];
    const int tid = threadIdx.x, wid = tid >> 5, lane = tid & 31;
    const int g = lane >> 2, tig = lane & 3;
    const int wm = (wid & 3) << 4;        // 0,16,32,48
    const int wn = (wid >> 2) * 96;       // 0,96,192,288
    const int m0 = blockIdx.x * 64;

    // A staging: 1 float4/thread: row = tid>>3, k offset akq = (tid&7)*4
    const int arow = tid >> 3, akq = (tid & 7) << 2;
    const float* asrc = x + (m0 + arow) * C_ + akq;
    // slot addr for element j: asts + j*136  (sp = j, e = (akq>>2)&1)
    const int asts = ((akq >> 3) * 4 * 68 + arow) * 2 + ((akq >> 2) & 1);

    // B staging: 6 float4/thread
    const float* bsrc[6];
    int bsts[6];
#pragma unroll
    for (int i = 0; i < 6; i++) {
        int ci = i * 512 + tid;
        int k = ci / 96, nq = (ci - k * 96) * 4;
        int head = nq >> 7, col = nq & 127;
        const float* W = (head == 0) ? Wq : (head == 1) ? Wk : Wv;
        bsrc[i] = W + k * H_ + col;
        bsts[i] = (((k >> 3) * 4 + (k & 3)) * 388 + nq) * 2 + ((k >> 2) & 1);
    }

    float acc[12][4];
#pragma unroll
    for (int nt = 0; nt < 12; nt++)
#pragma unroll
        for (int i = 0; i < 4; i++) acc[nt][i] = 0.f;

    float4 ar;
    float4 br[6];

    // prologue: load + store stage 0
    ar = *(const float4*)asrc;
#pragma unroll
    for (int i = 0; i < 6; i++) br[i] = *(const float4*)bsrc[i];
    {
        float* A = sm;
        float* Bb = sm + PJ_A;
        A[asts + 0 * 136] = to_tf32(ar.x);
        A[asts + 1 * 136] = to_tf32(ar.y);
        A[asts + 2 * 136] = to_tf32(ar.z);
        A[asts + 3 * 136] = to_tf32(ar.w);
#pragma unroll
        for (int i = 0; i < 6; i++) {
            Bb[bsts[i] + 0] = to_tf32(br[i].x);
            Bb[bsts[i] + 2] = to_tf32(br[i].y);
            Bb[bsts[i] + 4] = to_tf32(br[i].z);
            Bb[bsts[i] + 6] = to_tf32(br[i].w);
        }
    }
    __syncthreads();

    for (int s = 0; s < 32; s++) {
        const float* A  = sm + (s & 1) * PJ_STAGE;
        const float* Bb = A + PJ_A;
        // issue gmem loads for next slab (overlap with MMA below)
        if (s + 1 < 32) {
            int k0 = (s + 1) * 32;
            ar = *(const float4*)(asrc + k0);
#pragma unroll
            for (int i = 0; i < 6; i++)
                br[i] = *(const float4*)(bsrc[i] + k0 * H_);
        }
#pragma unroll
        for (int kkb = 0; kkb < 4; kkb++) {
            float2 va0 = *(const float2*)&A[((kkb * 4 + tig) * 68 + wm + g) * 2];
            float2 va1 = *(const float2*)&A[((kkb * 4 + tig) * 68 + wm + g + 8) * 2];
            uint32_t a[4] = {fu(va0.x), fu(va1.x), fu(va0.y), fu(va1.y)};
#pragma unroll
            for (int nt = 0; nt < 12; nt++) {
                float2 vb = *(const float2*)
                    &Bb[((kkb * 4 + tig) * 388 + wn + nt * 8 + g) * 2];
                mma_tf32(acc[nt], a, fu(vb.x), fu(vb.y));
            }
        }
        if (s + 1 < 32) {
            float* An = sm + ((s + 1) & 1) * PJ_STAGE;
            float* Bn = An + PJ_A;
            An[asts + 0 * 136] = to_tf32(ar.x);
            An[asts + 1 * 136] = to_tf32(ar.y);
            An[asts + 2 * 136] = to_tf32(ar.z);
            An[asts + 3 * 136] = to_tf32(ar.w);
#pragma unroll
            for (int i = 0; i < 6; i++) {
                Bn[bsts[i] + 0] = to_tf32(br[i].x);
                Bn[bsts[i] + 2] = to_tf32(br[i].y);
                Bn[bsts[i] + 4] = to_tf32(br[i].z);
                Bn[bsts[i] + 6] = to_tf32(br[i].w);
            }
        }
        __syncthreads();
    }

    // epilogue: tf32-rounded stores into g_Q/g_K/g_V
#pragma unroll
    for (int nt = 0; nt < 12; nt++) {
        int cn = wn + nt * 8 + tig * 2;
        float* outp = (cn < 128) ? g_Q : (cn < 256) ? g_K : g_V;
        int col = cn & 127;
        int r = m0 + wm + g;
        *(float2*)&outp[r * H_ + col] =
            make_float2(to_tf32(acc[nt][0]), to_tf32(acc[nt][1]));
        *(float2*)&outp[(r + 8) * H_ + col] =
            make_float2(to_tf32(acc[nt][2]), to_tf32(acc[nt][3]));
    }
}

// ---------------------------------------------------------------------------
// Kernel 2: attention partial (split-K flash), TF32 mma, cp.async pipeline.
// smem (floats): Q 8192 (swz128) | K 8192 (swz128) | V 8448 (pad 132,
// corr at col 128) | P 4096 (swz64).  Total 115712 B -> 2 CTAs/SM.
// Pipeline: V(t) load overlaps S-mma; K(t+1) load overlaps softmax+PV.
// ---------------------------------------------------------------------------
#define AQ_  0
#define AK_  8192
#define AV_  16384
#define AP_  24832
#define ATTN_SMEM (28928 * 4)   // 115712 B

__global__ __launch_bounds__(256, 2) void attn_part() {
    extern __shared__ float sma[];
    float* smQ = sma + AQ_;
    float* smK = sma + AK_;
    float* smV = sma + AV_;
    float* smP = sma + AP_;
    const uint32_t sbase = smem_u32(sma);

    const int bx = blockIdx.x;
    const int b = bx / 80;
    const int u = bx % 80;
    int qt, ch;
    if (u < 8)       { qt = u;                  ch = 0; }
    else if (u < 24) { qt = 8 + ((u - 8) >> 1); ch = (u - 8) & 1; }
    else if (u < 48) { int v = u - 24; qt = 16 + v / 3; ch = v - 3 * (v / 3); }
    else             { int v = u - 48; qt = 24 + (v >> 2); ch = v & 3; }
    const int m0 = qt * 64;
    const int t0 = ch * 8;
    const int t1 = min(t0 + 8, qt + 1);

    const float* __restrict__ Qg = g_Q + (b * T_ + m0) * H_;
    const float* __restrict__ Kg = g_K + b * T_ * H_;
    const float* __restrict__ Vg = g_V + b * T_ * H_;

    const int tid = threadIdx.x;
    const int wid = tid >> 5, lane = tid & 31;
    const int g = lane >> 2, tig = lane & 3;
    const int wm  = (wid & 3) << 4;
    const int wns = (wid >> 2) << 5;
    const int wno = (wid >> 2) << 6;
    const int ty = tid >> 4, tx = tid & 15;
    const int r0 = ty << 2, c0s = tx << 2;

    const int lrow = wid;              // chunk row base (tid>>5)
    const int lc = (tid & 31) << 2;    // chunk col (floats)

    // prologue: async Q (group), async K(t0) (group)
#pragma unroll
    for (int i = 0; i < 8; i++) {
        int row = i * 8 + lrow;
        CP16(sbase + (uint32_t)(AQ_ + swz128(row, lc)) * 4, Qg + row * H_ + lc);
    }
    CPCOMMIT();
#pragma unroll
    for (int i = 0; i < 8; i++) {
        int row = i * 8 + lrow;
        CP16(sbase + (uint32_t)(AK_ + swz128(row, lc)) * 4,
             Kg + (t0 * 64 + row) * H_ + lc);
    }
    CPCOMMIT();

    float m_run[4], l_run[4];
#pragma unroll
    for (int i = 0; i < 4; i++) { m_run[i] = -1e30f; l_run[i] = 0.f; }
    float oacc[8][4];
#pragma unroll
    for (int nt = 0; nt < 8; nt++)
#pragma unroll
        for (int i = 0; i < 4; i++) oacc[nt][i] = 0.f;

    const float inv_scale = 0.03125f;  // C^-0.5

    for (int t = t0; t < t1; t++) {
        __syncthreads();   // PV(t-1) done CTA-wide -> Vbuf free
        // issue V(t) async (overlaps S-mma)
#pragma unroll
        for (int i = 0; i < 8; i++) {
            int row = i * 8 + lrow;
            CP16(sbase + (uint32_t)(AV_ + row * 132 + lc) * 4,
                 Vg + (t * 64 + row) * H_ + lc);
        }
        CPCOMMIT();
        CPWAIT(1);         // K(t) (and Q) arrived; V may be in flight
        __syncthreads();

        // S = Q @ K^T  (warp 16x32, 4 n-tiles)
        float sacc[4][4];
#pragma unroll
        for (int nt = 0; nt < 4; nt++)
#pragma unroll
            for (int i = 0; i < 4; i++) sacc[nt][i] = 0.f;

#pragma unroll 4
        for (int kk = 0; kk < 128; kk += 8) {
            uint32_t a[4];
            a[0] = fu(smQ[swz128(wm + g,     kk + tig)]);
            a[1] = fu(smQ[swz128(wm + g + 8, kk + tig)]);
            a[2] = fu(smQ[swz128(wm + g,     kk + tig + 4)]);
            a[3] = fu(smQ[swz128(wm + g + 8, kk + tig + 4)]);
#pragma unroll
            for (int nt = 0; nt < 4; nt++) {
                uint32_t b0 = fu(smK[swz128(wns + nt * 8 + g, kk + tig)]);
                uint32_t b1 = fu(smK[swz128(wns + nt * 8 + g, kk + tig + 4)]);
                mma_tf32(sacc[nt], a, b0, b1);
            }
        }
        __syncthreads();   // all warps done reading smK
        // prefetch K(t+1) (overlaps softmax + PV)
        if (t + 1 < t1) {
#pragma unroll
            for (int i = 0; i < 8; i++) {
                int row = i * 8 + lrow;
                CP16(sbase + (uint32_t)(AK_ + swz128(row, lc)) * 4,
                     Kg + ((t + 1) * 64 + row) * H_ + lc);
            }
            CPCOMMIT();
        }

        // write scaled (+ masked) S into smP
        const int rA = wm + g, rB = wm + g + 8;
        const bool diag = (t == qt);
#pragma unroll
        for (int nt = 0; nt < 4; nt++) {
            int cn = wns + nt * 8 + tig * 2;
            float v0 = sacc[nt][0] * inv_scale;
            float v1 = sacc[nt][1] * inv_scale;
            float v2 = sacc[nt][2] * inv_scale;
            float v3 = sacc[nt][3] * inv_scale;
            if (diag) {
                if (cn > rA)     v0 = -1e30f;
                if (cn + 1 > rA) v1 = -1e30f;
                if (cn > rB)     v2 = -1e30f;
                if (cn + 1 > rB) v3 = -1e30f;
            }
            *(float2*)&smP[swz64(rA, cn)] = make_float2(v0, v1);
            *(float2*)&smP[swz64(rB, cn)] = make_float2(v2, v3);
        }
        __syncthreads();

        // online softmax (row stats across 16-thread groups)
#pragma unroll
        for (int i = 0; i < 4; i++) {
            float4 sv = *(const float4*)&smP[swz64(r0 + i, c0s)];
            float mx = fmaxf(fmaxf(sv.x, sv.y), fmaxf(sv.z, sv.w));
            mx = fmaxf(mx, __shfl_xor_sync(0xffffffffu, mx, 8));
            mx = fmaxf(mx, __shfl_xor_sync(0xffffffffu, mx, 4));
            mx = fmaxf(mx, __shfl_xor_sync(0xffffffffu, mx, 2));
            mx = fmaxf(mx, __shfl_xor_sync(0xffffffffu, mx, 1));
            float mnew = fmaxf(m_run[i], mx);
            float corr = __expf(m_run[i] - mnew);
            m_run[i] = mnew;
            float p0 = __expf(sv.x - mnew), p1 = __expf(sv.y - mnew);
            float p2 = __expf(sv.z - mnew), p3 = __expf(sv.w - mnew);
            float ps = p0 + p1 + p2 + p3;
            *(float4*)&smP[swz64(r0 + i, c0s)] =
                make_float4(to_tf32(p0), to_tf32(p1), to_tf32(p2), to_tf32(p3));
            ps += __shfl_xor_sync(0xffffffffu, ps, 8);
            ps += __shfl_xor_sync(0xffffffffu, ps, 4);
            ps += __shfl_xor_sync(0xffffffffu, ps, 2);
            ps += __shfl_xor_sync(0xffffffffu, ps, 1);
            l_run[i] = l_run[i] * corr + ps;
            if (tx == 0) smV[(r0 + i) * 132 + 128] = corr;  // corr in V padding
        }
        if (t + 1 < t1) { CPWAIT(1); } else { CPWAIT(0); }  // V(t) arrived
        __syncthreads();   // P, corr, V visible CTA-wide

        // rescale O, then O += P @ V (warp 16x64, 8 n-tiles)
        float cA = smV[(wm + g) * 132 + 128];
        float cB = smV[(wm + g + 8) * 132 + 128];
#pragma unroll
        for (int nt = 0; nt < 8; nt++) {
            oacc[nt][0] *= cA; oacc[nt][1] *= cA;
            oacc[nt][2] *= cB; oacc[nt][3] *= cB;
        }
#pragma unroll
        for (int kk = 0; kk < 64; kk += 8) {
            uint32_t a[4];
            a[0] = fu(smP[swz64(wm + g,     kk + tig)]);
            a[1] = fu(smP[swz64(wm + g + 8, kk + tig)]);
            a[2] = fu(smP[swz64(wm + g,     kk + tig + 4)]);
            a[3] = fu(smP[swz64(wm + g + 8, kk + tig + 4)]);
#pragma unroll
            for (int nt = 0; nt < 8; nt++) {
                uint32_t b0 = fu(smV[(kk + tig) * 132 + wno + nt * 8 + g]);
                uint32_t b1 = fu(smV[(kk + tig + 4) * 132 + wno + nt * 8 + g]);
                mma_tf32(oacc[nt], a, b0, b1);
            }
        }
    }

    // write unnormalized partials + per-row (m, l)
    const int p = bx;
    if (tx == 0) {
#pragma unroll
        for (int i = 0; i < 4; i++) {
            g_ml[(p * 64 + r0 + i) * 2 + 0] = m_run[i];
            g_ml[(p * 64 + r0 + i) * 2 + 1] = l_run[i];
        }
    }
#pragma unroll
    for (int nt = 0; nt < 8; nt++) {
        int cc = wno + nt * 8 + tig * 2;
        *(float2*)&g_Opart[(p * 64 + wm + g) * H_ + cc] =
            make_float2(oacc[nt][0], oacc[nt][1]);
        *(float2*)&g_Opart[(p * 64 + wm + g + 8) * H_ + cc] =
            make_float2(oacc[nt][2], oacc[nt][3]);
    }
}

// ---------------------------------------------------------------------------
// Kernel 3: merge partials -> final out
// ---------------------------------------------------------------------------
__global__ void attn_merge(float* __restrict__ out) {
    const int qt = blockIdx.x, b = blockIdx.y;
    const int nch = (qt >> 3) + 1;
    const int ubase = (qt < 8)  ? qt
                    : (qt < 16) ? 8 + 2 * (qt - 8)
                    : (qt < 24) ? 24 + 3 * (qt - 16)
                                : 48 + 4 * (qt - 24);
    const int pbase = b * 80 + ubase;
    const int tid = threadIdx.x;
    const int r = tid >> 2;
    const int c0 = (tid & 3) * 32;

    float m = -1e30f;
    for (int c = 0; c < nch; c++)
        m = fmaxf(m, g_ml[((pbase + c) * 64 + r) * 2]);
    float wgt[4];
    float l = 0.f;
    for (int c = 0; c < nch; c++) {
        wgt[c] = __expf(g_ml[((pbase + c) * 64 + r) * 2] - m);
        l += wgt[c] * g_ml[((pbase + c) * 64 + r) * 2 + 1];
    }
    const float invl = 1.f / l;
    const int orow = (b * T_ + qt * 64 + r) * H_;

    for (int cc = 0; cc < 32; cc += 4) {
        float ax = 0.f, ay = 0.f, az = 0.f, aw = 0.f;
        for (int c = 0; c < nch; c++) {
            float4 v = *(const float4*)&g_Opart[((pbase + c) * 64 + r) * H_ + c0 + cc];
            ax += wgt[c] * v.x; ay += wgt[c] * v.y;
            az += wgt[c] * v.z; aw += wgt[c] * v.w;
        }
        *(float4*)&out[orow + c0 + cc] =
            make_float4(ax * invl, ay * invl, az * invl, aw * invl);
    }
}

// ---------------------------------------------------------------------------
// Launch
// ---------------------------------------------------------------------------
extern "C" void kernel_launch(void* const* d_in, const int* in_sizes, int n_in,
                              void* d_out, int out_size) {
    const float* x  = (const float*)d_in[0];
    const float* Wq = (const float*)d_in[1];
    const float* Wk = (const float*)d_in[2];
    const float* Wv = (const float*)d_in[3];
    // d_in[4] = mask: tril by construction -> causal logic used directly.
    float* out = (float*)d_out;

    cudaFuncSetAttribute((const void*)proj_mma,
                         cudaFuncAttributeMaxDynamicSharedMemorySize, PJ_SMEM);
    proj_mma<<<BT_ / 64, 512, PJ_SMEM>>>(x, Wq, Wk, Wv);

    cudaFuncSetAttribute((const void*)attn_part,
                         cudaFuncAttributeMaxDynamicSharedMemorySize, ATTN_SMEM);
    attn_part<<<NUNITS, 256, ATTN_SMEM>>>();

    attn_merge<<<dim3(T_ / 64, B_), 256>>>(out);
}

// round 7
// speedup vs baseline: 1.3981x; 1.3981x over previous
#include <cuda_runtime.h>
#include <cstdint>

#define B_  4
#define T_  2048
#define C_  1024
#define H_  128
#define BT_ (B_ * T_)
#define NUNITS 320   // split-K attention work units: 4 batches * 80

// Static device scratch (allocation-free). g_Q/K/V hold tf32-rounded values.
__device__ float g_Q[BT_ * H_];
__device__ float g_K[BT_ * H_];
__device__ float g_V[BT_ * H_];
__device__ float g_Wt[3 * H_ * C_];          // W transposed [w][n][k], tf32
__device__ float g_Opart[NUNITS * 64 * H_];  // unnormalized partial O
__device__ float g_ml[NUNITS * 64 * 2];      // per-row (m, l)

// ---------------------------------------------------------------------------
// Helpers
// ---------------------------------------------------------------------------
__device__ __forceinline__ float to_tf32(float x) {
    float r; asm("cvt.rna.tf32.f32 %0, %1;" : "=f"(r) : "f"(x)); return r;
}
__device__ __forceinline__ uint32_t fu(float x) { return __float_as_uint(x); }

__device__ __forceinline__ void mma_tf32(float* d, const uint32_t* a,
                                         uint32_t b0, uint32_t b1) {
    asm volatile(
        "mma.sync.aligned.m16n8k8.row.col.f32.tf32.tf32.f32 "
        "{%0,%1,%2,%3}, {%4,%5,%6,%7}, {%8,%9}, {%0,%1,%2,%3};"
        : "+f"(d[0]), "+f"(d[1]), "+f"(d[2]), "+f"(d[3])
        : "r"(a[0]), "r"(a[1]), "r"(a[2]), "r"(a[3]), "r"(b0), "r"(b1));
}
// ldmatrix x4 b16: one 8x8-b16 tile == one 8x4-tf32 tile; x4 == exact
// m16k8 A-frag (rows,k-halves) or 2 consecutive n8k8 B-frags for [n][k] smem.
__device__ __forceinline__ void ldsm4(uint32_t* r, uint32_t addr) {
    asm volatile("ldmatrix.sync.aligned.m8n8.x4.shared.b16 {%0,%1,%2,%3}, [%4];"
                 : "=r"(r[0]), "=r"(r[1]), "=r"(r[2]), "=r"(r[3]) : "r"(addr));
}
__device__ __forceinline__ uint32_t smem_u32(const void* p) {
    uint32_t a;
    asm("{ .reg .u64 t; cvta.to.shared.u64 t, %1; cvt.u32.u64 %0, t; }"
        : "=r"(a) : "l"(p));
    return a;
}

#define CP16(dst, src) \
    asm volatile("cp.async.cg.shared.global [%0], [%1], 16;" \
                 :: "r"(dst), "l"(src) : "memory")
#define CPCOMMIT() asm volatile("cp.async.commit_group;" ::: "memory")
#define CPWAIT(n)  asm volatile("cp.async.wait_group %0;" :: "n"(n) : "memory")

// XOR-swizzled row-major layouts (conflict-free 16B chunks, no padding)
__device__ __forceinline__ int swz128(int r, int c) {
    return r * 128 + (c ^ ((r & 7) << 2));
}
__device__ __forceinline__ int swz64(int r, int c) {
    return r * 64 + (c ^ ((r & 7) << 2));
}
__device__ __forceinline__ int swz32(int r, int c) {
    return r * 32 + (c ^ ((r & 7) << 2));
}

// ---------------------------------------------------------------------------
// Kernel 0: transpose + tf32-round W [C,H] -> g_Wt [w][H][C]
// ---------------------------------------------------------------------------
__global__ void transpose_w(const float* __restrict__ Wq,
                            const float* __restrict__ Wk,
                            const float* __restrict__ Wv) {
    __shared__ float tile[32][33];
    const int w = blockIdx.z;
    const float* __restrict__ W = (w == 0) ? Wq : (w == 1) ? Wk : Wv;
    const int k0 = blockIdx.x * 32, n0 = blockIdx.y * 32;
    const int tx = threadIdx.x, ty = threadIdx.y;  // 32 x 8
#pragma unroll
    for (int i = 0; i < 32; i += 8)
        tile[ty + i][tx] = W[(k0 + ty + i) * H_ + n0 + tx];
    __syncthreads();
#pragma unroll
    for (int i = 0; i < 32; i += 8)
        g_Wt[w * H_ * C_ + (n0 + ty + i) * C_ + k0 + tx] =
            to_tf32(tile[tx][ty + i]);
}

// ---------------------------------------------------------------------------
// Kernel 1: QKV projection, TF32 mma.sync + ldmatrix + 3-stage cp.async.
// CTA 128(M) x 128(N), per-W via blockIdx.y, grid (64,3). 256 thr, 8 warps
// 4M x 2N, warp tile 32x64. smem/stage: A[128][32] + B[128][32] ([n][k]),
// swz32, 32KB; 3 stages = 96KB -> 2 CTAs/SM.
// ---------------------------------------------------------------------------
#define PJ_STG 8192                 // floats per stage (A 4096 | B 4096)
#define PJ_SMEM (3 * PJ_STG * 4)    // 98304 B

__global__ __launch_bounds__(256, 2) void proj_mma(
    const float* __restrict__ x)
{
    extern __shared__ float sm[];
    const uint32_t sbase = smem_u32(sm);
    const int tid = threadIdx.x, wid = tid >> 5, lane = tid & 31;
    const int g = lane >> 2, tig = lane & 3;
    const int wm = (wid & 3) << 5;        // 0,32,64,96
    const int wn = (wid >> 2) << 6;       // 0,64
    const int m0 = blockIdx.x * 128;
    const int w  = blockIdx.y;
    const float* __restrict__ Wt = g_Wt + w * H_ * C_;
    float* outp = (w == 0) ? g_Q : (w == 1) ? g_K : g_V;

    // cp.async staging: per thread 4 A chunks + 4 B chunks (16B each).
    // chunk i: row = i*32 + (tid>>3), c4 = tid&7  (row&7 invariant in i).
    const int r8 = tid >> 3, c4 = tid & 7;
    const float* srcA = x + (m0 + r8) * C_ + c4 * 4;
    const float* srcB = Wt + r8 * C_ + c4 * 4;
    const int dA = swz32(r8, c4 * 4);              // + i*1024
    const int dB = 4096 + dA;

    // ldmatrix addresses (per-kk col computed in-loop; bases here)
    const int arow = wm + (lane & 15);             // + msub*16
    const int acb  = (lane >> 4) << 2;
    const int brow = wn + (lane & 7) + ((lane >> 4) << 3);  // + pair*16
    const int bcb  = ((lane >> 3) & 1) << 2;

    float acc[2][8][4];
#pragma unroll
    for (int mt = 0; mt < 2; mt++)
#pragma unroll
        for (int nt = 0; nt < 8; nt++)
#pragma unroll
            for (int i = 0; i < 4; i++) acc[mt][nt][i] = 0.f;

    // prologue: stages 0,1
#pragma unroll
    for (int s = 0; s < 2; s++) {
        const uint32_t st = sbase + (uint32_t)(s * PJ_STG) * 4;
        const int k0 = s * 32;
#pragma unroll
        for (int i = 0; i < 4; i++) {
            CP16(st + (uint32_t)(dA + i * 1024) * 4, srcA + i * 32 * C_ + k0);
            CP16(st + (uint32_t)(dB + i * 1024) * 4, srcB + i * 32 * C_ + k0);
        }
        CPCOMMIT();
    }

    for (int s = 0; s < 32; s++) {
        CPWAIT(1);
        __syncthreads();
        const uint32_t st = sbase + (uint32_t)((s % 3) * PJ_STG) * 4;
#pragma unroll
        for (int kk = 0; kk < 32; kk += 8) {
            uint32_t a[2][4];
#pragma unroll
            for (int mt = 0; mt < 2; mt++) {
                ldsm4(a[mt], st + (uint32_t)swz32(arow + mt * 16, kk + acb) * 4);
                a[mt][0] = fu(to_tf32(__uint_as_float(a[mt][0])));
                a[mt][1] = fu(to_tf32(__uint_as_float(a[mt][1])));
                a[mt][2] = fu(to_tf32(__uint_as_float(a[mt][2])));
                a[mt][3] = fu(to_tf32(__uint_as_float(a[mt][3])));
            }
#pragma unroll
            for (int p = 0; p < 4; p++) {      // nt pairs (2p, 2p+1)
                uint32_t b[4];
                ldsm4(b, st + (uint32_t)(4096 + swz32(brow + p * 16, kk + bcb)) * 4);
                mma_tf32(acc[0][2 * p],     a[0], b[0], b[1]);
                mma_tf32(acc[1][2 * p],     a[1], b[0], b[1]);
                mma_tf32(acc[0][2 * p + 1], a[0], b[2], b[3]);
                mma_tf32(acc[1][2 * p + 1], a[1], b[2], b[3]);
            }
        }
        if (s + 2 < 32) {
            const uint32_t stn = sbase + (uint32_t)(((s + 2) % 3) * PJ_STG) * 4;
            const int k0 = (s + 2) * 32;
#pragma unroll
            for (int i = 0; i < 4; i++) {
                CP16(stn + (uint32_t)(dA + i * 1024) * 4, srcA + i * 32 * C_ + k0);
                CP16(stn + (uint32_t)(dB + i * 1024) * 4, srcB + i * 32 * C_ + k0);
            }
        }
        CPCOMMIT();   // commit every iter (empty groups ok) keeps wait counts aligned
    }

    // epilogue: tf32-rounded stores
#pragma unroll
    for (int mt = 0; mt < 2; mt++)
#pragma unroll
        for (int nt = 0; nt < 8; nt++) {
            int r = m0 + wm + mt * 16 + g;
            int cc = wn + nt * 8 + tig * 2;
            *(float2*)&outp[r * H_ + cc] =
                make_float2(to_tf32(acc[mt][nt][0]), to_tf32(acc[mt][nt][1]));
            *(float2*)&outp[(r + 8) * H_ + cc] =
                make_float2(to_tf32(acc[mt][nt][2]), to_tf32(acc[mt][nt][3]));
        }
}

// ---------------------------------------------------------------------------
// Kernel 2: attention partial (split-K flash), TF32 mma + ldmatrix,
// cp.async pipeline (V(t) overlaps S-mma; K(t+1) overlaps softmax+PV).
// smem floats: Q 8192 swz128 | K 8192 swz128 | V 8448 ([k][n] pad132, corr
// col128) | P 4096 swz64.  115712 B -> 2 CTAs/SM.
// ---------------------------------------------------------------------------
#define AQ_  0
#define AK_  8192
#define AV_  16384
#define AP_  24832
#define ATTN_SMEM (28928 * 4)

__global__ __launch_bounds__(256, 2) void attn_part() {
    extern __shared__ float sma[];
    float* smV = sma + AV_;
    float* smP = sma + AP_;
    const uint32_t sbase = smem_u32(sma);

    const int bx = blockIdx.x;
    const int b = bx / 80;
    const int u = bx % 80;
    int qt, ch;
    if (u < 8)       { qt = u;                  ch = 0; }
    else if (u < 24) { qt = 8 + ((u - 8) >> 1); ch = (u - 8) & 1; }
    else if (u < 48) { int v = u - 24; qt = 16 + v / 3; ch = v - 3 * (v / 3); }
    else             { int v = u - 48; qt = 24 + (v >> 2); ch = v & 3; }
    const int m0 = qt * 64;
    const int t0 = ch * 8;
    const int t1 = min(t0 + 8, qt + 1);

    const float* __restrict__ Qg = g_Q + (b * T_ + m0) * H_;
    const float* __restrict__ Kg = g_K + b * T_ * H_;
    const float* __restrict__ Vg = g_V + b * T_ * H_;

    const int tid = threadIdx.x;
    const int wid = tid >> 5, lane = tid & 31;
    const int g = lane >> 2, tig = lane & 3;
    const int wm  = (wid & 3) << 4;
    const int wns = (wid >> 2) << 5;
    const int wno = (wid >> 2) << 6;
    const int ty = tid >> 4, tx = tid & 15;
    const int r0 = ty << 2, c0s = tx << 2;

    // ldmatrix bases
    const int arow = wm + (lane & 15);
    const int acb  = (lane >> 4) << 2;
    const int brow = wns + (lane & 7) + ((lane >> 4) << 3);  // + pair*16
    const int bcb  = ((lane >> 3) & 1) << 2;

    const int lrow = wid;              // cp chunk row base
    const int lc = (tid & 31) << 2;    // cp chunk col (floats)

    // prologue: async Q, async K(t0)
#pragma unroll
    for (int i = 0; i < 8; i++) {
        int row = i * 8 + lrow;
        CP16(sbase + (uint32_t)(AQ_ + swz128(row, lc)) * 4, Qg + row * H_ + lc);
    }
    CPCOMMIT();
#pragma unroll
    for (int i = 0; i < 8; i++) {
        int row = i * 8 + lrow;
        CP16(sbase + (uint32_t)(AK_ + swz128(row, lc)) * 4,
             Kg + (t0 * 64 + row) * H_ + lc);
    }
    CPCOMMIT();

    float m_run[4], l_run[4];
#pragma unroll
    for (int i = 0; i < 4; i++) { m_run[i] = -1e30f; l_run[i] = 0.f; }
    float oacc[8][4];
#pragma unroll
    for (int nt = 0; nt < 8; nt++)
#pragma unroll
        for (int i = 0; i < 4; i++) oacc[nt][i] = 0.f;

    const float inv_scale = 0.03125f;  // C^-0.5

    for (int t = t0; t < t1; t++) {
        __syncthreads();   // PV(t-1) done -> V buffer free
#pragma unroll
        for (int i = 0; i < 8; i++) {
            int row = i * 8 + lrow;
            CP16(sbase + (uint32_t)(AV_ + row * 132 + lc) * 4,
                 Vg + (t * 64 + row) * H_ + lc);
        }
        CPCOMMIT();
        CPWAIT(1);         // K(t) (and Q) arrived
        __syncthreads();

        // S = Q @ K^T  (warp 16x32): per kk 1 ldsm(A) + 2 ldsm(B, 2nt each)
        float sacc[4][4];
#pragma unroll
        for (int nt = 0; nt < 4; nt++)
#pragma unroll
            for (int i = 0; i < 4; i++) sacc[nt][i] = 0.f;

#pragma unroll 4
        for (int kk = 0; kk < 128; kk += 8) {
            uint32_t a[4];
            ldsm4(a, sbase + (uint32_t)(AQ_ + swz128(arow, kk + acb)) * 4);
#pragma unroll
            for (int p = 0; p < 2; p++) {
                uint32_t bb[4];
                ldsm4(bb, sbase + (uint32_t)(AK_ + swz128(brow + p * 16, kk + bcb)) * 4);
                mma_tf32(sacc[2 * p],     a, bb[0], bb[1]);
                mma_tf32(sacc[2 * p + 1], a, bb[2], bb[3]);
            }
        }
        __syncthreads();   // all warps done reading smK
        if (t + 1 < t1) {  // prefetch K(t+1) (overlaps softmax + PV)
#pragma unroll
            for (int i = 0; i < 8; i++) {
                int row = i * 8 + lrow;
                CP16(sbase + (uint32_t)(AK_ + swz128(row, lc)) * 4,
                     Kg + ((t + 1) * 64 + row) * H_ + lc);
            }
            CPCOMMIT();
        }

        // write scaled (+ masked) S into smP
        const int rA = wm + g, rB = wm + g + 8;
        const bool diag = (t == qt);
#pragma unroll
        for (int nt = 0; nt < 4; nt++) {
            int cn = wns + nt * 8 + tig * 2;
            float v0 = sacc[nt][0] * inv_scale;
            float v1 = sacc[nt][1] * inv_scale;
            float v2 = sacc[nt][2] * inv_scale;
            float v3 = sacc[nt][3] * inv_scale;
            if (diag) {
                if (cn > rA)     v0 = -1e30f;
                if (cn + 1 > rA) v1 = -1e30f;
                if (cn > rB)     v2 = -1e30f;
                if (cn + 1 > rB) v3 = -1e30f;
            }
            *(float2*)&smP[swz64(rA, cn)] = make_float2(v0, v1);
            *(float2*)&smP[swz64(rB, cn)] = make_float2(v2, v3);
        }
        __syncthreads();

        // online softmax (row stats across 16-thread groups)
#pragma unroll
        for (int i = 0; i < 4; i++) {
            float4 sv = *(const float4*)&smP[swz64(r0 + i, c0s)];
            float mx = fmaxf(fmaxf(sv.x, sv.y), fmaxf(sv.z, sv.w));
            mx = fmaxf(mx, __shfl_xor_sync(0xffffffffu, mx, 8));
            mx = fmaxf(mx, __shfl_xor_sync(0xffffffffu, mx, 4));
            mx = fmaxf(mx, __shfl_xor_sync(0xffffffffu, mx, 2));
            mx = fmaxf(mx, __shfl_xor_sync(0xffffffffu, mx, 1));
            float mnew = fmaxf(m_run[i], mx);
            float corr = __expf(m_run[i] - mnew);
            m_run[i] = mnew;
            float p0 = __expf(sv.x - mnew), p1 = __expf(sv.y - mnew);
            float p2 = __expf(sv.z - mnew), p3 = __expf(sv.w - mnew);
            float ps = p0 + p1 + p2 + p3;
            *(float4*)&smP[swz64(r0 + i, c0s)] =
                make_float4(to_tf32(p0), to_tf32(p1), to_tf32(p2), to_tf32(p3));
            ps += __shfl_xor_sync(0xffffffffu, ps, 8);
            ps += __shfl_xor_sync(0xffffffffu, ps, 4);
            ps += __shfl_xor_sync(0xffffffffu, ps, 2);
            ps += __shfl_xor_sync(0xffffffffu, ps, 1);
            l_run[i] = l_run[i] * corr + ps;
            if (tx == 0) smV[(r0 + i) * 132 + 128] = corr;  // corr in V padding
        }
        if (t + 1 < t1) { CPWAIT(1); } else { CPWAIT(0); }  // V(t) arrived
        __syncthreads();

        // rescale O, then O += P @ V (warp 16x64); P frags via ldmatrix
        float cA = smV[(wm + g) * 132 + 128];
        float cB = smV[(wm + g + 8) * 132 + 128];
#pragma unroll
        for (int nt = 0; nt < 8; nt++) {
            oacc[nt][0] *= cA; oacc[nt][1] *= cA;
            oacc[nt][2] *= cB; oacc[nt][3] *= cB;
        }
#pragma unroll
        for (int kk = 0; kk < 64; kk += 8) {
            uint32_t a[4];
            ldsm4(a, sbase + (uint32_t)(AP_ + swz64(arow, kk + acb)) * 4);
#pragma unroll
            for (int nt = 0; nt < 8; nt++) {
                uint32_t b0 = fu(smV[(kk + tig) * 132 + wno + nt * 8 + g]);
                uint32_t b1 = fu(smV[(kk + tig + 4) * 132 + wno + nt * 8 + g]);
                mma_tf32(oacc[nt], a, b0, b1);
            }
        }
    }

    // write unnormalized partials + per-row (m, l)
    const int p = bx;
    if (tx == 0) {
#pragma unroll
        for (int i = 0; i < 4; i++) {
            g_ml[(p * 64 + r0 + i) * 2 + 0] = m_run[i];
            g_ml[(p * 64 + r0 + i) * 2 + 1] = l_run[i];
        }
    }
#pragma unroll
    for (int nt = 0; nt < 8; nt++) {
        int cc = wno + nt * 8 + tig * 2;
        *(float2*)&g_Opart[(p * 64 + wm + g) * H_ + cc] =
            make_float2(oacc[nt][0], oacc[nt][1]);
        *(float2*)&g_Opart[(p * 64 + wm + g + 8) * H_ + cc] =
            make_float2(oacc[nt][2], oacc[nt][3]);
    }
}

// ---------------------------------------------------------------------------
// Kernel 3: merge partials -> final out
// ---------------------------------------------------------------------------
__global__ void attn_merge(float* __restrict__ out) {
    const int qt = blockIdx.x, b = blockIdx.y;
    const int nch = (qt >> 3) + 1;
    const int ubase = (qt < 8)  ? qt
                    : (qt < 16) ? 8 + 2 * (qt - 8)
                    : (qt < 24) ? 24 + 3 * (qt - 16)
                                : 48 + 4 * (qt - 24);
    const int pbase = b * 80 + ubase;
    const int tid = threadIdx.x;
    const int r = tid >> 2;
    const int c0 = (tid & 3) * 32;

    float m = -1e30f;
    for (int c = 0; c < nch; c++)
        m = fmaxf(m, g_ml[((pbase + c) * 64 + r) * 2]);
    float wgt[4];
    float l = 0.f;
    for (int c = 0; c < nch; c++) {
        wgt[c] = __expf(g_ml[((pbase + c) * 64 + r) * 2] - m);
        l += wgt[c] * g_ml[((pbase + c) * 64 + r) * 2 + 1];
    }
    const float invl = 1.f / l;
    const int orow = (b * T_ + qt * 64 + r) * H_;

    for (int cc = 0; cc < 32; cc += 4) {
        float ax = 0.f, ay = 0.f, az = 0.f, aw = 0.f;
        for (int c = 0; c < nch; c++) {
            float4 v = *(const float4*)&g_Opart[((pbase + c) * 64 + r) * H_ + c0 + cc];
            ax += wgt[c] * v.x; ay += wgt[c] * v.y;
            az += wgt[c] * v.z; aw += wgt[c] * v.w;
        }
        *(float4*)&out[orow + c0 + cc] =
            make_float4(ax * invl, ay * invl, az * invl, aw * invl);
    }
}

// ---------------------------------------------------------------------------
// Launch
// ---------------------------------------------------------------------------
extern "C" void kernel_launch(void* const* d_in, const int* in_sizes, int n_in,
                              void* d_out, int out_size) {
    const float* x  = (const float*)d_in[0];
    const float* Wq = (const float*)d_in[1];
    const float* Wk = (const float*)d_in[2];
    const float* Wv = (const float*)d_in[3];
    // d_in[4] = mask: tril by construction -> causal logic used directly.
    float* out = (float*)d_out;

    dim3 gt(C_ / 32, H_ / 32, 3);
    transpose_w<<<gt, dim3(32, 8)>>>(Wq, Wk, Wv);

    cudaFuncSetAttribute((const void*)proj_mma,
                         cudaFuncAttributeMaxDynamicSharedMemorySize, PJ_SMEM);
    proj_mma<<<dim3(BT_ / 128, 3), 256, PJ_SMEM>>>(x);

    cudaFuncSetAttribute((const void*)attn_part,
                         cudaFuncAttributeMaxDynamicSharedMemorySize, ATTN_SMEM);
    attn_part<<<NUNITS, 256, ATTN_SMEM>>>();

    attn_merge<<<dim3(T_ / 64, B_), 256>>>(out);
}

// round 8
// speedup vs baseline: 1.6773x; 1.1998x over previous
#include <cuda_runtime.h>
#include <cstdint>

#define B_  4
#define T_  2048
#define C_  1024
#define H_  128
#define BT_ (B_ * T_)
#define NUNITS 320   // split-K attention work units: 4 batches * 80

// Static device scratch (allocation-free). g_Q/K/V hold tf32-rounded values.
__device__ float g_Q[BT_ * H_];
__device__ float g_K[BT_ * H_];
__device__ float g_V[BT_ * H_];
__device__ float g_Wt[3 * H_ * C_];          // W transposed [w][n][k], tf32 (=[384][1024])
__device__ float g_Opart[NUNITS * 64 * H_];  // unnormalized partial O
__device__ float g_ml[NUNITS * 64 * 2];      // per-row (m, l)

// ---------------------------------------------------------------------------
// Helpers
// ---------------------------------------------------------------------------
__device__ __forceinline__ float to_tf32(float x) {
    float r; asm("cvt.rna.tf32.f32 %0, %1;" : "=f"(r) : "f"(x)); return r;
}
__device__ __forceinline__ uint32_t fu(float x) { return __float_as_uint(x); }

__device__ __forceinline__ void mma_tf32(float* d, const uint32_t* a,
                                         uint32_t b0, uint32_t b1) {
    asm volatile(
        "mma.sync.aligned.m16n8k8.row.col.f32.tf32.tf32.f32 "
        "{%0,%1,%2,%3}, {%4,%5,%6,%7}, {%8,%9}, {%0,%1,%2,%3};"
        : "+f"(d[0]), "+f"(d[1]), "+f"(d[2]), "+f"(d[3])
        : "r"(a[0]), "r"(a[1]), "r"(a[2]), "r"(a[3]), "r"(b0), "r"(b1));
}
__device__ __forceinline__ void ldsm4(uint32_t* r, uint32_t addr) {
    asm volatile("ldmatrix.sync.aligned.m8n8.x4.shared.b16 {%0,%1,%2,%3}, [%4];"
                 : "=r"(r[0]), "=r"(r[1]), "=r"(r[2]), "=r"(r[3]) : "r"(addr));
}
__device__ __forceinline__ uint32_t smem_u32(const void* p) {
    uint32_t a;
    asm("{ .reg .u64 t; cvta.to.shared.u64 t, %1; cvt.u32.u64 %0, t; }"
        : "=r"(a) : "l"(p));
    return a;
}

#define CP16(dst, src) \
    asm volatile("cp.async.cg.shared.global [%0], [%1], 16;" \
                 :: "r"(dst), "l"(src) : "memory")
#define CPCOMMIT() asm volatile("cp.async.commit_group;" ::: "memory")
#define CPWAIT(n)  asm volatile("cp.async.wait_group %0;" :: "n"(n) : "memory")

// XOR-swizzled row-major layouts (conflict-free 16B chunks, no padding)
__device__ __forceinline__ int swz128(int r, int c) {
    return r * 128 + (c ^ ((r & 7) << 2));
}
__device__ __forceinline__ int swz64(int r, int c) {
    return r * 64 + (c ^ ((r & 7) << 2));
}
__device__ __forceinline__ int swz32(int r, int c) {
    return r * 32 + (c ^ ((r & 7) << 2));
}

// ---------------------------------------------------------------------------
// Kernel 0: transpose + tf32-round W [C,H] -> g_Wt [w][H][C]
// ---------------------------------------------------------------------------
__global__ void transpose_w(const float* __restrict__ Wq,
                            const float* __restrict__ Wk,
                            const float* __restrict__ Wv) {
    __shared__ float tile[32][33];
    const int w = blockIdx.z;
    const float* __restrict__ W = (w == 0) ? Wq : (w == 1) ? Wk : Wv;
    const int k0 = blockIdx.x * 32, n0 = blockIdx.y * 32;
    const int tx = threadIdx.x, ty = threadIdx.y;  // 32 x 8
#pragma unroll
    for (int i = 0; i < 32; i += 8)
        tile[ty + i][tx] = W[(k0 + ty + i) * H_ + n0 + tx];
    __syncthreads();
#pragma unroll
    for (int i = 0; i < 32; i += 8)
        g_Wt[w * H_ * C_ + (n0 + ty + i) * C_ + k0 + tx] =
            to_tf32(tile[tx][ty + i]);
}

// ---------------------------------------------------------------------------
// Kernel 1: fused QKV projection, TF32 mma + ldmatrix + 3-stage cp.async.
// CTA 64(M) x 384(N = Q|K|V), grid 128 (single clean wave). 256 thr,
// 8 warps 2M x 4N, warp tile 32x96 (12 nt). Stage: A[64][32] + B[384][32]
// ([n][k]), swz32, 56KB; 3 stages = 168KB -> 1 CTA/SM.
// ---------------------------------------------------------------------------
#define PJ_STG 14336                // floats per stage (A 2048 | B 12288)
#define PJ_SMEM (3 * PJ_STG * 4)    // 172032 B

__global__ __launch_bounds__(256, 1) void proj_mma(const float* __restrict__ x)
{
    extern __shared__ float sm[];
    const uint32_t sbase = smem_u32(sm);
    const int tid = threadIdx.x, wid = tid >> 5, lane = tid & 31;
    const int g = lane >> 2, tig = lane & 3;
    const int wm = (wid & 1) << 5;        // 0,32
    const int wn = (wid >> 1) * 96;       // 0,96,192,288
    const int m0 = blockIdx.x * 64;

    // cp.async staging: per thread 2 A chunks + 12 B chunks (16B each)
    const int r8 = tid >> 3, c4 = tid & 7;            // r8 0..31
    const float* srcA = x + (m0 + r8) * C_ + c4 * 4;
    const float* srcB = g_Wt + r8 * C_ + c4 * 4;
    const int dA = swz32(r8, c4 * 4);                 // + i*1024
    const int dB = 2048 + dA;                         // + i*1024

    // ldmatrix bases
    const int arow = wm + (lane & 15);                // + mt*16
    const int acb  = (lane >> 4) << 2;
    const int brow = wn + (lane & 7) + ((lane >> 4) << 3);  // + pair*16
    const int bcb  = ((lane >> 3) & 1) << 2;

    float acc[2][12][4];
#pragma unroll
    for (int mt = 0; mt < 2; mt++)
#pragma unroll
        for (int nt = 0; nt < 12; nt++)
#pragma unroll
            for (int i = 0; i < 4; i++) acc[mt][nt][i] = 0.f;

    // prologue: stages 0,1
#pragma unroll
    for (int s = 0; s < 2; s++) {
        const uint32_t st = sbase + (uint32_t)(s * PJ_STG) * 4;
        const int k0 = s * 32;
#pragma unroll
        for (int i = 0; i < 2; i++)
            CP16(st + (uint32_t)(dA + i * 1024) * 4, srcA + i * 32 * C_ + k0);
#pragma unroll
        for (int i = 0; i < 12; i++)
            CP16(st + (uint32_t)(dB + i * 1024) * 4, srcB + i * 32 * C_ + k0);
        CPCOMMIT();
    }

    for (int s = 0; s < 32; s++) {
        CPWAIT(1);
        __syncthreads();
        const uint32_t st = sbase + (uint32_t)((s % 3) * PJ_STG) * 4;
#pragma unroll
        for (int kk = 0; kk < 32; kk += 8) {
            uint32_t a[2][4];
#pragma unroll
            for (int mt = 0; mt < 2; mt++) {
                ldsm4(a[mt], st + (uint32_t)swz32(arow + mt * 16, kk + acb) * 4);
#pragma unroll
                for (int i = 0; i < 4; i++)
                    a[mt][i] = fu(to_tf32(__uint_as_float(a[mt][i])));
            }
#pragma unroll
            for (int p = 0; p < 6; p++) {      // nt pairs (2p, 2p+1)
                uint32_t b[4];
                ldsm4(b, st + (uint32_t)(2048 + swz32(brow + p * 16, kk + bcb)) * 4);
                mma_tf32(acc[0][2 * p],     a[0], b[0], b[1]);
                mma_tf32(acc[1][2 * p],     a[1], b[0], b[1]);
                mma_tf32(acc[0][2 * p + 1], a[0], b[2], b[3]);
                mma_tf32(acc[1][2 * p + 1], a[1], b[2], b[3]);
            }
        }
        if (s + 2 < 32) {
            const uint32_t stn = sbase + (uint32_t)(((s + 2) % 3) * PJ_STG) * 4;
            const int k0 = (s + 2) * 32;
#pragma unroll
            for (int i = 0; i < 2; i++)
                CP16(stn + (uint32_t)(dA + i * 1024) * 4, srcA + i * 32 * C_ + k0);
#pragma unroll
            for (int i = 0; i < 12; i++)
                CP16(stn + (uint32_t)(dB + i * 1024) * 4, srcB + i * 32 * C_ + k0);
        }
        CPCOMMIT();   // commit every iter keeps wait counts aligned
    }

    // epilogue: tf32-rounded stores to Q/K/V
#pragma unroll
    for (int mt = 0; mt < 2; mt++)
#pragma unroll
        for (int nt = 0; nt < 12; nt++) {
            int n = wn + nt * 8 + tig * 2;
            float* outp = (n < 128) ? g_Q : (n < 256) ? g_K : g_V;
            int col = n & 127;
            int r = m0 + wm + mt * 16 + g;
            *(float2*)&outp[r * H_ + col] =
                make_float2(to_tf32(acc[mt][nt][0]), to_tf32(acc[mt][nt][1]));
            *(float2*)&outp[(r + 8) * H_ + col] =
                make_float2(to_tf32(acc[mt][nt][2]), to_tf32(acc[mt][nt][3]));
        }
}

// ---------------------------------------------------------------------------
// Kernel 2: attention partial (split-K flash), TF32 mma + ldmatrix,
// IN-REGISTER softmax in the MMA fragment layout (rows wm+g, wm+g+8);
// cross-warp-half stat exchange lives in V padding cols 128..131.
// smem floats: Q 8192 swz128 | K 8192 swz128 | V 8448 ([k][n] stride132)
// | P 4096 swz64.  Total 115712 B -> 2 CTAs/SM (exact fit incl. 1KB resv).
// ---------------------------------------------------------------------------
#define AQ_  0
#define AK_  8192
#define AV_  16384
#define AP_  24832
#define ATTN_SMEM (28928 * 4)

__global__ __launch_bounds__(256, 2) void attn_part() {
    extern __shared__ float sma[];
    float* smV = sma + AV_;
    float* smP = sma + AP_;
    const uint32_t sbase = smem_u32(sma);

    const int bx = blockIdx.x;
    const int b = bx / 80;
    const int u = bx % 80;
    int qt, ch;
    if (u < 8)       { qt = u;                  ch = 0; }
    else if (u < 24) { qt = 8 + ((u - 8) >> 1); ch = (u - 8) & 1; }
    else if (u < 48) { int v = u - 24; qt = 16 + v / 3; ch = v - 3 * (v / 3); }
    else             { int v = u - 48; qt = 24 + (v >> 2); ch = v & 3; }
    const int m0 = qt * 64;
    const int t0 = ch * 8;
    const int t1 = min(t0 + 8, qt + 1);

    const float* __restrict__ Qg = g_Q + (b * T_ + m0) * H_;
    const float* __restrict__ Kg = g_K + b * T_ * H_;
    const float* __restrict__ Vg = g_V + b * T_ * H_;

    const int tid = threadIdx.x;
    const int wid = tid >> 5, lane = tid & 31;
    const int g = lane >> 2, tig = lane & 3;
    const int wm   = (wid & 3) << 4;
    const int wns  = (wid >> 2) << 5;
    const int wno  = (wid >> 2) << 6;
    const int half = wid >> 2;
    const int rA = wm + g, rB = wm + g + 8;

    // ldmatrix bases
    const int arow = wm + (lane & 15);
    const int acb  = (lane >> 4) << 2;
    const int brow = wns + (lane & 7) + ((lane >> 4) << 3);
    const int bcb  = ((lane >> 3) & 1) << 2;

    const int lrow = wid;              // cp chunk row base
    const int lc = (tid & 31) << 2;    // cp chunk col (floats)

    // prologue: async Q, async K(t0)
#pragma unroll
    for (int i = 0; i < 8; i++) {
        int row = i * 8 + lrow;
        CP16(sbase + (uint32_t)(AQ_ + swz128(row, lc)) * 4, Qg + row * H_ + lc);
    }
    CPCOMMIT();
#pragma unroll
    for (int i = 0; i < 8; i++) {
        int row = i * 8 + lrow;
        CP16(sbase + (uint32_t)(AK_ + swz128(row, lc)) * 4,
             Kg + (t0 * 64 + row) * H_ + lc);
    }
    CPCOMMIT();

    float m_run2[2] = {-1e30f, -1e30f};
    float l_run2[2] = {0.f, 0.f};
    float oacc[8][4];
#pragma unroll
    for (int nt = 0; nt < 8; nt++)
#pragma unroll
        for (int i = 0; i < 4; i++) oacc[nt][i] = 0.f;

    const float inv_scale = 0.03125f;  // C^-0.5

    for (int t = t0; t < t1; t++) {
        __syncthreads();   // PV(t-1) done -> V buffer + P free
#pragma unroll
        for (int i = 0; i < 8; i++) {
            int row = i * 8 + lrow;
            CP16(sbase + (uint32_t)(AV_ + row * 132 + lc) * 4,
                 Vg + (t * 64 + row) * H_ + lc);
        }
        CPCOMMIT();
        CPWAIT(1);         // K(t) (and Q) arrived
        __syncthreads();

        // S = Q @ K^T  (warp 16x32)
        float sacc[4][4];
#pragma unroll
        for (int nt = 0; nt < 4; nt++)
#pragma unroll
            for (int i = 0; i < 4; i++) sacc[nt][i] = 0.f;

#pragma unroll 4
        for (int kk = 0; kk < 128; kk += 8) {
            uint32_t a[4];
            ldsm4(a, sbase + (uint32_t)(AQ_ + swz128(arow, kk + acb)) * 4);
#pragma unroll
            for (int p = 0; p < 2; p++) {
                uint32_t bb[4];
                ldsm4(bb, sbase + (uint32_t)(AK_ + swz128(brow + p * 16, kk + bcb)) * 4);
                mma_tf32(sacc[2 * p],     a, bb[0], bb[1]);
                mma_tf32(sacc[2 * p + 1], a, bb[2], bb[3]);
            }
        }

        // scale + causal mask in fragment layout
        const bool diag = (t == qt);
#pragma unroll
        for (int nt = 0; nt < 4; nt++) {
            int cn = wns + nt * 8 + tig * 2;
            sacc[nt][0] *= inv_scale;
            sacc[nt][1] *= inv_scale;
            sacc[nt][2] *= inv_scale;
            sacc[nt][3] *= inv_scale;
            if (diag) {
                if (cn > rA)     sacc[nt][0] = -1e30f;
                if (cn + 1 > rA) sacc[nt][1] = -1e30f;
                if (cn > rB)     sacc[nt][2] = -1e30f;
                if (cn + 1 > rB) sacc[nt][3] = -1e30f;
            }
        }

        // row max: 8 local vals + quad shfl (tig bits = lane bits 0,1)
        float pmaxA = -1e30f, pmaxB = -1e30f;
#pragma unroll
        for (int nt = 0; nt < 4; nt++) {
            pmaxA = fmaxf(pmaxA, fmaxf(sacc[nt][0], sacc[nt][1]));
            pmaxB = fmaxf(pmaxB, fmaxf(sacc[nt][2], sacc[nt][3]));
        }
        pmaxA = fmaxf(pmaxA, __shfl_xor_sync(0xffffffffu, pmaxA, 1));
        pmaxA = fmaxf(pmaxA, __shfl_xor_sync(0xffffffffu, pmaxA, 2));
        pmaxB = fmaxf(pmaxB, __shfl_xor_sync(0xffffffffu, pmaxB, 1));
        pmaxB = fmaxf(pmaxB, __shfl_xor_sync(0xffffffffu, pmaxB, 2));
        if (tig == 0) {
            smV[rA * 132 + 128 + half] = pmaxA;
            smV[rB * 132 + 128 + half] = pmaxB;
        }
        __syncthreads();   // stats visible + all warps done reading smK

        if (t + 1 < t1) {  // prefetch K(t+1) (overlaps softmax + PV)
#pragma unroll
            for (int i = 0; i < 8; i++) {
                int row = i * 8 + lrow;
                CP16(sbase + (uint32_t)(AK_ + swz128(row, lc)) * 4,
                     Kg + ((t + 1) * 64 + row) * H_ + lc);
            }
        }
        CPCOMMIT();

        // combine halves, online-softmax update
        float mxA = fmaxf(pmaxA, smV[rA * 132 + 128 + (1 - half)]);
        float mxB = fmaxf(pmaxB, smV[rB * 132 + 128 + (1 - half)]);
        float mnewA = fmaxf(m_run2[0], mxA);
        float mnewB = fmaxf(m_run2[1], mxB);
        float corrA = __expf(m_run2[0] - mnewA);
        float corrB = __expf(m_run2[1] - mnewB);
        m_run2[0] = mnewA; m_run2[1] = mnewB;

        float psumA = 0.f, psumB = 0.f;
#pragma unroll
        for (int nt = 0; nt < 4; nt++) {
            int cn = wns + nt * 8 + tig * 2;
            float p0 = __expf(sacc[nt][0] - mnewA);
            float p1 = __expf(sacc[nt][1] - mnewA);
            float p2 = __expf(sacc[nt][2] - mnewB);
            float p3 = __expf(sacc[nt][3] - mnewB);
            psumA += p0 + p1;
            psumB += p2 + p3;
            *(float2*)&smP[swz64(rA, cn)] = make_float2(to_tf32(p0), to_tf32(p1));
            *(float2*)&smP[swz64(rB, cn)] = make_float2(to_tf32(p2), to_tf32(p3));
        }
        psumA += __shfl_xor_sync(0xffffffffu, psumA, 1);
        psumA += __shfl_xor_sync(0xffffffffu, psumA, 2);
        psumB += __shfl_xor_sync(0xffffffffu, psumB, 1);
        psumB += __shfl_xor_sync(0xffffffffu, psumB, 2);
        if (tig == 0) {
            smV[rA * 132 + 130 + half] = psumA;
            smV[rB * 132 + 130 + half] = psumB;
        }
        if (t + 1 < t1) { CPWAIT(1); } else { CPWAIT(0); }  // V(t) arrived
        __syncthreads();   // P + sums + V visible

        l_run2[0] = l_run2[0] * corrA + psumA + smV[rA * 132 + 130 + (1 - half)];
        l_run2[1] = l_run2[1] * corrB + psumB + smV[rB * 132 + 130 + (1 - half)];

        // rescale O (rows rA, rB local!), then O += P @ V (warp 16x64)
#pragma unroll
        for (int nt = 0; nt < 8; nt++) {
            oacc[nt][0] *= corrA; oacc[nt][1] *= corrA;
            oacc[nt][2] *= corrB; oacc[nt][3] *= corrB;
        }
#pragma unroll
        for (int kk = 0; kk < 64; kk += 8) {
            uint32_t a[4];
            ldsm4(a, sbase + (uint32_t)(AP_ + swz64(arow, kk + acb)) * 4);
#pragma unroll
            for (int nt = 0; nt < 8; nt++) {
                uint32_t b0 = fu(smV[(kk + tig) * 132 + wno + nt * 8 + g]);
                uint32_t b1 = fu(smV[(kk + tig + 4) * 132 + wno + nt * 8 + g]);
                mma_tf32(oacc[nt], a, b0, b1);
            }
        }
    }

    // write unnormalized partials + per-row (m, l)
    const int p = bx;
    if (tig == 0 && half == 0) {
        g_ml[(p * 64 + rA) * 2 + 0] = m_run2[0];
        g_ml[(p * 64 + rA) * 2 + 1] = l_run2[0];
        g_ml[(p * 64 + rB) * 2 + 0] = m_run2[1];
        g_ml[(p * 64 + rB) * 2 + 1] = l_run2[1];
    }
#pragma unroll
    for (int nt = 0; nt < 8; nt++) {
        int cc = wno + nt * 8 + tig * 2;
        *(float2*)&g_Opart[(p * 64 + rA) * H_ + cc] =
            make_float2(oacc[nt][0], oacc[nt][1]);
        *(float2*)&g_Opart[(p * 64 + rB) * H_ + cc] =
            make_float2(oacc[nt][2], oacc[nt][3]);
    }
}

// ---------------------------------------------------------------------------
// Kernel 3: merge partials -> final out.  One float4 per thread; 262144
// threads total (1024 CTAs x 256) -> DRAM-bound, fully parallel.
// ---------------------------------------------------------------------------
__global__ __launch_bounds__(256) void attn_merge(float* __restrict__ out) {
    const int gidx = blockIdx.x * 256 + threadIdx.x;
    const int row = gidx >> 5;           // 0..8191
    const int c0 = (gidx & 31) << 2;     // float4 col
    const int b = row >> 11, rr = row & 2047;
    const int qt = rr >> 6, r = rr & 63;
    const int nch = (qt >> 3) + 1;
    const int ubase = (qt < 8)  ? qt
                    : (qt < 16) ? 8 + 2 * (qt - 8)
                    : (qt < 24) ? 24 + 3 * (qt - 16)
                                : 48 + 4 * (qt - 24);
    const int pbase = b * 80 + ubase;

    float m = -1e30f;
#pragma unroll 4
    for (int c = 0; c < nch; c++)
        m = fmaxf(m, g_ml[((pbase + c) * 64 + r) * 2]);
    float l = 0.f;
    float ax = 0.f, ay = 0.f, az = 0.f, aw = 0.f;
#pragma unroll 4
    for (int c = 0; c < nch; c++) {
        float wgt = __expf(g_ml[((pbase + c) * 64 + r) * 2] - m);
        l += wgt * g_ml[((pbase + c) * 64 + r) * 2 + 1];
        float4 v = *(const float4*)&g_Opart[((pbase + c) * 64 + r) * H_ + c0];
        ax += wgt * v.x; ay += wgt * v.y; az += wgt * v.z; aw += wgt * v.w;
    }
    const float invl = 1.f / l;
    *(float4*)&out[row * H_ + c0] =
        make_float4(ax * invl, ay * invl, az * invl, aw * invl);
}

// ---------------------------------------------------------------------------
// Launch
// ---------------------------------------------------------------------------
extern "C" void kernel_launch(void* const* d_in, const int* in_sizes, int n_in,
                              void* d_out, int out_size) {
    const float* x  = (const float*)d_in[0];
    const float* Wq = (const float*)d_in[1];
    const float* Wk = (const float*)d_in[2];
    const float* Wv = (const float*)d_in[3];
    // d_in[4] = mask: tril by construction -> causal logic used directly.
    float* out = (float*)d_out;

    dim3 gt(C_ / 32, H_ / 32, 3);
    transpose_w<<<gt, dim3(32, 8)>>>(Wq, Wk, Wv);

    cudaFuncSetAttribute((const void*)proj_mma,
                         cudaFuncAttributeMaxDynamicSharedMemorySize, PJ_SMEM);
    proj_mma<<<BT_ / 64, 256, PJ_SMEM>>>(x);

    cudaFuncSetAttribute((const void*)attn_part,
                         cudaFuncAttributeMaxDynamicSharedMemorySize, ATTN_SMEM);
    attn_part<<<NUNITS, 256, ATTN_SMEM>>>();

    attn_merge<<<BT_ * H_ / 4 / 256, 256>>>(out);
}

// round 9
// speedup vs baseline: 1.7071x; 1.0177x over previous
#include <cuda_runtime.h>
#include <cstdint>

#define B_  4
#define T_  2048
#define C_  1024
#define H_  128
#define BT_ (B_ * T_)
#define UPB 144      // units per batch, chunk=4: sum ceil((qt+1)/4), qt 0..31
#define NUNITS (B_ * UPB)   // 576

// Static device scratch (allocation-free). g_Q/K/V hold tf32-rounded values.
__device__ float g_Q[BT_ * H_];
__device__ float g_K[BT_ * H_];
__device__ float g_V[BT_ * H_];
__device__ float g_Wt[3 * H_ * C_];          // W transposed [w][n][k], tf32
__device__ float g_Opart[NUNITS * 64 * H_];  // unnormalized partial O
__device__ float g_ml[NUNITS * 64 * 2];      // per-row (m, l)

// ---------------------------------------------------------------------------
// Helpers
// ---------------------------------------------------------------------------
__device__ __forceinline__ float to_tf32(float x) {
    float r; asm("cvt.rna.tf32.f32 %0, %1;" : "=f"(r) : "f"(x)); return r;
}
__device__ __forceinline__ uint32_t fu(float x) { return __float_as_uint(x); }

__device__ __forceinline__ void mma_tf32(float* d, const uint32_t* a,
                                         uint32_t b0, uint32_t b1) {
    asm volatile(
        "mma.sync.aligned.m16n8k8.row.col.f32.tf32.tf32.f32 "
        "{%0,%1,%2,%3}, {%4,%5,%6,%7}, {%8,%9}, {%0,%1,%2,%3};"
        : "+f"(d[0]), "+f"(d[1]), "+f"(d[2]), "+f"(d[3])
        : "r"(a[0]), "r"(a[1]), "r"(a[2]), "r"(a[3]), "r"(b0), "r"(b1));
}
__device__ __forceinline__ void ldsm4(uint32_t* r, uint32_t addr) {
    asm volatile("ldmatrix.sync.aligned.m8n8.x4.shared.b16 {%0,%1,%2,%3}, [%4];"
                 : "=r"(r[0]), "=r"(r[1]), "=r"(r[2]), "=r"(r[3]) : "r"(addr));
}
__device__ __forceinline__ uint32_t smem_u32(const void* p) {
    uint32_t a;
    asm("{ .reg .u64 t; cvta.to.shared.u64 t, %1; cvt.u32.u64 %0, t; }"
        : "=r"(a) : "l"(p));
    return a;
}

#define CP16(dst, src) \
    asm volatile("cp.async.cg.shared.global [%0], [%1], 16;" \
                 :: "r"(dst), "l"(src) : "memory")
#define CPCOMMIT() asm volatile("cp.async.commit_group;" ::: "memory")
#define CPWAIT(n)  asm volatile("cp.async.wait_group %0;" :: "n"(n) : "memory")

// XOR-swizzled row-major layouts (conflict-free 16B chunks, no padding)
__device__ __forceinline__ int swz128(int r, int c) {
    return r * 128 + (c ^ ((r & 7) << 2));
}
__device__ __forceinline__ int swz64(int r, int c) {
    return r * 64 + (c ^ ((r & 7) << 2));
}
__device__ __forceinline__ int swz32(int r, int c) {
    return r * 32 + (c ^ ((r & 7) << 2));
}

// ---------------------------------------------------------------------------
// Kernel 0: transpose + tf32-round W [C,H] -> g_Wt [w][H][C]
// ---------------------------------------------------------------------------
__global__ void transpose_w(const float* __restrict__ Wq,
                            const float* __restrict__ Wk,
                            const float* __restrict__ Wv) {
    __shared__ float tile[32][33];
    const int w = blockIdx.z;
    const float* __restrict__ W = (w == 0) ? Wq : (w == 1) ? Wk : Wv;
    const int k0 = blockIdx.x * 32, n0 = blockIdx.y * 32;
    const int tx = threadIdx.x, ty = threadIdx.y;  // 32 x 8
#pragma unroll
    for (int i = 0; i < 32; i += 8)
        tile[ty + i][tx] = W[(k0 + ty + i) * H_ + n0 + tx];
    __syncthreads();
#pragma unroll
    for (int i = 0; i < 32; i += 8)
        g_Wt[w * H_ * C_ + (n0 + ty + i) * C_ + k0 + tx] =
            to_tf32(tile[tx][ty + i]);
}

// ---------------------------------------------------------------------------
// Kernel 1: fused QKV projection, TF32 mma + ldmatrix + 3-stage cp.async.
// CTA 64(M) x 384(N = Q|K|V), grid 128. 256 thr, 8 warps 2M x 4N,
// warp tile 32x96. Stage: A[64][32] + B[384][32] ([n][k]), swz32, 56KB;
// 3 stages = 168KB -> 1 CTA/SM.
// ---------------------------------------------------------------------------
#define PJ_STG 14336
#define PJ_SMEM (3 * PJ_STG * 4)    // 172032 B

__global__ __launch_bounds__(256, 1) void proj_mma(const float* __restrict__ x)
{
    extern __shared__ float sm[];
    const uint32_t sbase = smem_u32(sm);
    const int tid = threadIdx.x, wid = tid >> 5, lane = tid & 31;
    const int g = lane >> 2, tig = lane & 3;
    const int wm = (wid & 1) << 5;
    const int wn = (wid >> 1) * 96;
    const int m0 = blockIdx.x * 64;

    const int r8 = tid >> 3, c4 = tid & 7;
    const float* srcA = x + (m0 + r8) * C_ + c4 * 4;
    const float* srcB = g_Wt + r8 * C_ + c4 * 4;
    const int dA = swz32(r8, c4 * 4);
    const int dB = 2048 + dA;

    const int arow = wm + (lane & 15);
    const int acb  = (lane >> 4) << 2;
    const int brow = wn + (lane & 7) + ((lane >> 4) << 3);
    const int bcb  = ((lane >> 3) & 1) << 2;

    float acc[2][12][4];
#pragma unroll
    for (int mt = 0; mt < 2; mt++)
#pragma unroll
        for (int nt = 0; nt < 12; nt++)
#pragma unroll
            for (int i = 0; i < 4; i++) acc[mt][nt][i] = 0.f;

#pragma unroll
    for (int s = 0; s < 2; s++) {
        const uint32_t st = sbase + (uint32_t)(s * PJ_STG) * 4;
        const int k0 = s * 32;
#pragma unroll
        for (int i = 0; i < 2; i++)
            CP16(st + (uint32_t)(dA + i * 1024) * 4, srcA + i * 32 * C_ + k0);
#pragma unroll
        for (int i = 0; i < 12; i++)
            CP16(st + (uint32_t)(dB + i * 1024) * 4, srcB + i * 32 * C_ + k0);
        CPCOMMIT();
    }

    for (int s = 0; s < 32; s++) {
        CPWAIT(1);
        __syncthreads();
        const uint32_t st = sbase + (uint32_t)((s % 3) * PJ_STG) * 4;
#pragma unroll
        for (int kk = 0; kk < 32; kk += 8) {
            uint32_t a[2][4];
#pragma unroll
            for (int mt = 0; mt < 2; mt++) {
                ldsm4(a[mt], st + (uint32_t)swz32(arow + mt * 16, kk + acb) * 4);
#pragma unroll
                for (int i = 0; i < 4; i++)
                    a[mt][i] = fu(to_tf32(__uint_as_float(a[mt][i])));
            }
#pragma unroll
            for (int p = 0; p < 6; p++) {
                uint32_t b[4];
                ldsm4(b, st + (uint32_t)(2048 + swz32(brow + p * 16, kk + bcb)) * 4);
                mma_tf32(acc[0][2 * p],     a[0], b[0], b[1]);
                mma_tf32(acc[1][2 * p],     a[1], b[0], b[1]);
                mma_tf32(acc[0][2 * p + 1], a[0], b[2], b[3]);
                mma_tf32(acc[1][2 * p + 1], a[1], b[2], b[3]);
            }
        }
        if (s + 2 < 32) {
            const uint32_t stn = sbase + (uint32_t)(((s + 2) % 3) * PJ_STG) * 4;
            const int k0 = (s + 2) * 32;
#pragma unroll
            for (int i = 0; i < 2; i++)
                CP16(stn + (uint32_t)(dA + i * 1024) * 4, srcA + i * 32 * C_ + k0);
#pragma unroll
            for (int i = 0; i < 12; i++)
                CP16(stn + (uint32_t)(dB + i * 1024) * 4, srcB + i * 32 * C_ + k0);
        }
        CPCOMMIT();
    }

#pragma unroll
    for (int mt = 0; mt < 2; mt++)
#pragma unroll
        for (int nt = 0; nt < 12; nt++) {
            int n = wn + nt * 8 + tig * 2;
            float* outp = (n < 128) ? g_Q : (n < 256) ? g_K : g_V;
            int col = n & 127;
            int r = m0 + wm + mt * 16 + g;
            *(float2*)&outp[r * H_ + col] =
                make_float2(to_tf32(acc[mt][nt][0]), to_tf32(acc[mt][nt][1]));
            *(float2*)&outp[(r + 8) * H_ + col] =
                make_float2(to_tf32(acc[mt][nt][2]), to_tf32(acc[mt][nt][3]));
        }
}

// ---------------------------------------------------------------------------
// Kernel 2: attention partial (split-K flash, chunk=4 -> 576 uniform units),
// TF32 mma + ldmatrix, in-register softmax in fragment layout.
// Unit decode: qt = 4a+r, ubase(qt) = (a+1)(2a+r); heavy-first issue order.
// smem floats: Q 8192 swz128 | K 8192 swz128 | V 8448 ([k][n] stride132,
// stats in cols 128..131) | P 4096 swz64.  115712 B -> 2 CTAs/SM.
// ---------------------------------------------------------------------------
#define AQ_  0
#define AK_  8192
#define AV_  16384
#define AP_  24832
#define ATTN_SMEM (28928 * 4)

__global__ __launch_bounds__(256, 2) void attn_part() {
    extern __shared__ float sma[];
    float* smV = sma + AV_;
    float* smP = sma + AP_;
    const uint32_t sbase = smem_u32(sma);

    // heavy-first: reverse unit order (high qt first)
    const int idx = (NUNITS - 1) - blockIdx.x;
    const int b = idx / UPB;
    const int u = idx % UPB;
    // invert ubase: a = floor((sqrt(2u+1)-1)/2), fixup for fp slop
    int a = (int)((sqrtf(2.f * u + 1.f) - 1.f) * 0.5f);
    if (2 * (a + 1) * (a + 2) <= u) a++;
    if (2 * a * (a + 1) > u) a--;
    const int rem = u - 2 * a * (a + 1);
    const int qt = 4 * a + rem / (a + 1);
    const int ch = rem - (rem / (a + 1)) * (a + 1);
    const int m0 = qt * 64;
    const int t0 = ch * 4;
    const int t1 = min(t0 + 4, qt + 1);

    const float* __restrict__ Qg = g_Q + (b * T_ + m0) * H_;
    const float* __restrict__ Kg = g_K + b * T_ * H_;
    const float* __restrict__ Vg = g_V + b * T_ * H_;

    const int tid = threadIdx.x;
    const int wid = tid >> 5, lane = tid & 31;
    const int g = lane >> 2, tig = lane & 3;
    const int wm   = (wid & 3) << 4;
    const int wns  = (wid >> 2) << 5;
    const int wno  = (wid >> 2) << 6;
    const int half = wid >> 2;
    const int rA = wm + g, rB = wm + g + 8;

    const int arow = wm + (lane & 15);
    const int acb  = (lane >> 4) << 2;
    const int brow = wns + (lane & 7) + ((lane >> 4) << 3);
    const int bcb  = ((lane >> 3) & 1) << 2;

    const int lrow = wid;
    const int lc = (tid & 31) << 2;

    // prologue: async Q, async K(t0)
#pragma unroll
    for (int i = 0; i < 8; i++) {
        int row = i * 8 + lrow;
        CP16(sbase + (uint32_t)(AQ_ + swz128(row, lc)) * 4, Qg + row * H_ + lc);
    }
    CPCOMMIT();
#pragma unroll
    for (int i = 0; i < 8; i++) {
        int row = i * 8 + lrow;
        CP16(sbase + (uint32_t)(AK_ + swz128(row, lc)) * 4,
             Kg + (t0 * 64 + row) * H_ + lc);
    }
    CPCOMMIT();

    float m_run2[2] = {-1e30f, -1e30f};
    float l_run2[2] = {0.f, 0.f};
    float oacc[8][4];
#pragma unroll
    for (int nt = 0; nt < 8; nt++)
#pragma unroll
        for (int i = 0; i < 4; i++) oacc[nt][i] = 0.f;

    const float inv_scale = 0.03125f;  // C^-0.5

    for (int t = t0; t < t1; t++) {
        __syncthreads();   // PV(t-1) done -> V buffer + P free
#pragma unroll
        for (int i = 0; i < 8; i++) {
            int row = i * 8 + lrow;
            CP16(sbase + (uint32_t)(AV_ + row * 132 + lc) * 4,
                 Vg + (t * 64 + row) * H_ + lc);
        }
        CPCOMMIT();
        CPWAIT(1);         // K(t) (and Q) arrived
        __syncthreads();

        // S = Q @ K^T  (warp 16x32)
        float sacc[4][4];
#pragma unroll
        for (int nt = 0; nt < 4; nt++)
#pragma unroll
            for (int i = 0; i < 4; i++) sacc[nt][i] = 0.f;

#pragma unroll 4
        for (int kk = 0; kk < 128; kk += 8) {
            uint32_t aa[4];
            ldsm4(aa, sbase + (uint32_t)(AQ_ + swz128(arow, kk + acb)) * 4);
#pragma unroll
            for (int p = 0; p < 2; p++) {
                uint32_t bb[4];
                ldsm4(bb, sbase + (uint32_t)(AK_ + swz128(brow + p * 16, kk + bcb)) * 4);
                mma_tf32(sacc[2 * p],     aa, bb[0], bb[1]);
                mma_tf32(sacc[2 * p + 1], aa, bb[2], bb[3]);
            }
        }

        // scale + causal mask in fragment layout
        const bool diag = (t == qt);
#pragma unroll
        for (int nt = 0; nt < 4; nt++) {
            int cn = wns + nt * 8 + tig * 2;
            sacc[nt][0] *= inv_scale;
            sacc[nt][1] *= inv_scale;
            sacc[nt][2] *= inv_scale;
            sacc[nt][3] *= inv_scale;
            if (diag) {
                if (cn > rA)     sacc[nt][0] = -1e30f;
                if (cn + 1 > rA) sacc[nt][1] = -1e30f;
                if (cn > rB)     sacc[nt][2] = -1e30f;
                if (cn + 1 > rB) sacc[nt][3] = -1e30f;
            }
        }

        // row max: quad shfl then cross-half via smem
        float pmaxA = -1e30f, pmaxB = -1e30f;
#pragma unroll
        for (int nt = 0; nt < 4; nt++) {
            pmaxA = fmaxf(pmaxA, fmaxf(sacc[nt][0], sacc[nt][1]));
            pmaxB = fmaxf(pmaxB, fmaxf(sacc[nt][2], sacc[nt][3]));
        }
        pmaxA = fmaxf(pmaxA, __shfl_xor_sync(0xffffffffu, pmaxA, 1));
        pmaxA = fmaxf(pmaxA, __shfl_xor_sync(0xffffffffu, pmaxA, 2));
        pmaxB = fmaxf(pmaxB, __shfl_xor_sync(0xffffffffu, pmaxB, 1));
        pmaxB = fmaxf(pmaxB, __shfl_xor_sync(0xffffffffu, pmaxB, 2));
        if (tig == 0) {
            smV[rA * 132 + 128 + half] = pmaxA;
            smV[rB * 132 + 128 + half] = pmaxB;
        }
        __syncthreads();   // stats visible + all warps done reading smK

        if (t + 1 < t1) {  // prefetch K(t+1) overlaps softmax + PV
#pragma unroll
            for (int i = 0; i < 8; i++) {
                int row = i * 8 + lrow;
                CP16(sbase + (uint32_t)(AK_ + swz128(row, lc)) * 4,
                     Kg + ((t + 1) * 64 + row) * H_ + lc);
            }
        }
        CPCOMMIT();

        float mxA = fmaxf(pmaxA, smV[rA * 132 + 128 + (1 - half)]);
        float mxB = fmaxf(pmaxB, smV[rB * 132 + 128 + (1 - half)]);
        float mnewA = fmaxf(m_run2[0], mxA);
        float mnewB = fmaxf(m_run2[1], mxB);
        float corrA = __expf(m_run2[0] - mnewA);
        float corrB = __expf(m_run2[1] - mnewB);
        m_run2[0] = mnewA; m_run2[1] = mnewB;

        float psumA = 0.f, psumB = 0.f;
#pragma unroll
        for (int nt = 0; nt < 4; nt++) {
            int cn = wns + nt * 8 + tig * 2;
            float p0 = __expf(sacc[nt][0] - mnewA);
            float p1 = __expf(sacc[nt][1] - mnewA);
            float p2 = __expf(sacc[nt][2] - mnewB);
            float p3 = __expf(sacc[nt][3] - mnewB);
            psumA += p0 + p1;
            psumB += p2 + p3;
            *(float2*)&smP[swz64(rA, cn)] = make_float2(to_tf32(p0), to_tf32(p1));
            *(float2*)&smP[swz64(rB, cn)] = make_float2(to_tf32(p2), to_tf32(p3));
        }
        psumA += __shfl_xor_sync(0xffffffffu, psumA, 1);
        psumA += __shfl_xor_sync(0xffffffffu, psumA, 2);
        psumB += __shfl_xor_sync(0xffffffffu, psumB, 1);
        psumB += __shfl_xor_sync(0xffffffffu, psumB, 2);
        if (tig == 0) {
            smV[rA * 132 + 130 + half] = psumA;
            smV[rB * 132 + 130 + half] = psumB;
        }
        if (t + 1 < t1) { CPWAIT(1); } else { CPWAIT(0); }  // V(t) arrived
        __syncthreads();

        l_run2[0] = l_run2[0] * corrA + psumA + smV[rA * 132 + 130 + (1 - half)];
        l_run2[1] = l_run2[1] * corrB + psumB + smV[rB * 132 + 130 + (1 - half)];

        // rescale O, then O += P @ V (warp 16x64)
#pragma unroll
        for (int nt = 0; nt < 8; nt++) {
            oacc[nt][0] *= corrA; oacc[nt][1] *= corrA;
            oacc[nt][2] *= corrB; oacc[nt][3] *= corrB;
        }
#pragma unroll
        for (int kk = 0; kk < 64; kk += 8) {
            uint32_t aa[4];
            ldsm4(aa, sbase + (uint32_t)(AP_ + swz64(arow, kk + acb)) * 4);
#pragma unroll
            for (int nt = 0; nt < 8; nt++) {
                uint32_t b0 = fu(smV[(kk + tig) * 132 + wno + nt * 8 + g]);
                uint32_t b1 = fu(smV[(kk + tig + 4) * 132 + wno + nt * 8 + g]);
                mma_tf32(oacc[nt], aa, b0, b1);
            }
        }
    }

    // write unnormalized partials + per-row (m, l)
    const int p = idx;
    if (tig == 0 && half == 0) {
        g_ml[(p * 64 + rA) * 2 + 0] = m_run2[0];
        g_ml[(p * 64 + rA) * 2 + 1] = l_run2[0];
        g_ml[(p * 64 + rB) * 2 + 0] = m_run2[1];
        g_ml[(p * 64 + rB) * 2 + 1] = l_run2[1];
    }
#pragma unroll
    for (int nt = 0; nt < 8; nt++) {
        int cc = wno + nt * 8 + tig * 2;
        *(float2*)&g_Opart[(p * 64 + rA) * H_ + cc] =
            make_float2(oacc[nt][0], oacc[nt][1]);
        *(float2*)&g_Opart[(p * 64 + rB) * H_ + cc] =
            make_float2(oacc[nt][2], oacc[nt][3]);
    }
}

// ---------------------------------------------------------------------------
// Kernel 3: merge partials -> final out.  One float4 per thread (1024 CTAs).
// ---------------------------------------------------------------------------
__global__ __launch_bounds__(256) void attn_merge(float* __restrict__ out) {
    const int gidx = blockIdx.x * 256 + threadIdx.x;
    const int row = gidx >> 5;           // 0..8191
    const int c0 = (gidx & 31) << 2;     // float4 col
    const int b = row >> 11, rr = row & 2047;
    const int qt = rr >> 6, r = rr & 63;
    const int a = qt >> 2, rm = qt & 3;
    const int nch = a + 1;                       // ceil((qt+1)/4)
    const int ubase = (a + 1) * (2 * a + rm);
    const int pbase = b * UPB + ubase;

    float m = -1e30f;
#pragma unroll 8
    for (int c = 0; c < nch; c++)
        m = fmaxf(m, g_ml[((pbase + c) * 64 + r) * 2]);
    float l = 0.f;
    float ax = 0.f, ay = 0.f, az = 0.f, aw = 0.f;
#pragma unroll 8
    for (int c = 0; c < nch; c++) {
        float wgt = __expf(g_ml[((pbase + c) * 64 + r) * 2] - m);
        l += wgt * g_ml[((pbase + c) * 64 + r) * 2 + 1];
        float4 v = *(const float4*)&g_Opart[((pbase + c) * 64 + r) * H_ + c0];
        ax += wgt * v.x; ay += wgt * v.y; az += wgt * v.z; aw += wgt * v.w;
    }
    const float invl = 1.f / l;
    *(float4*)&out[row * H_ + c0] =
        make_float4(ax * invl, ay * invl, az * invl, aw * invl);
}

// ---------------------------------------------------------------------------
// Launch
// ---------------------------------------------------------------------------
extern "C" void kernel_launch(void* const* d_in, const int* in_sizes, int n_in,
                              void* d_out, int out_size) {
    const float* x  = (const float*)d_in[0];
    const float* Wq = (const float*)d_in[1];
    const float* Wk = (const float*)d_in[2];
    const float* Wv = (const float*)d_in[3];
    // d_in[4] = mask: tril by construction -> causal logic used directly.
    float* out = (float*)d_out;

    dim3 gt(C_ / 32, H_ / 32, 3);
    transpose_w<<<gt, dim3(32, 8)>>>(Wq, Wk, Wv);

    cudaFuncSetAttribute((const void*)proj_mma,
                         cudaFuncAttributeMaxDynamicSharedMemorySize, PJ_SMEM);
    proj_mma<<<BT_ / 64, 256, PJ_SMEM>>>(x);

    cudaFuncSetAttribute((const void*)attn_part,
                         cudaFuncAttributeMaxDynamicSharedMemorySize, ATTN_SMEM);
    attn_part<<<NUNITS, 256, ATTN_SMEM>>>();

    attn_merge<<<BT_ * H_ / 4 / 256, 256>>>(out);
}

// round 10
// speedup vs baseline: 2.4594x; 1.4407x over previous
#include <cuda_runtime.h>
#include <cuda_fp16.h>
#include <cstdint>

#define B_  4
#define T_  2048
#define C_  1024
#define H_  128
#define BT_ (B_ * T_)
#define UPB 144      // units per batch, chunk=4
#define NUNITS (B_ * UPB)   // 576

// Static device scratch (allocation-free). Q/K/V/x/Wt held as fp16.
__device__ __half g_Xh[BT_ * C_];
__device__ __half g_Q[BT_ * H_];
__device__ __half g_K[BT_ * H_];
__device__ __half g_V[BT_ * H_];
__device__ __half g_Wt[3 * H_ * C_];         // W transposed [w][n][k]
__device__ float g_Opart[NUNITS * 64 * H_];  // unnormalized partial O (fp32)
__device__ float g_ml[NUNITS * 64 * 2];      // per-row (m, l)

// ---------------------------------------------------------------------------
// Helpers
// ---------------------------------------------------------------------------
__device__ __forceinline__ void mma_f16(float* d, const uint32_t* a,
                                        uint32_t b0, uint32_t b1) {
    asm volatile(
        "mma.sync.aligned.m16n8k16.row.col.f32.f16.f16.f32 "
        "{%0,%1,%2,%3}, {%4,%5,%6,%7}, {%8,%9}, {%0,%1,%2,%3};"
        : "+f"(d[0]), "+f"(d[1]), "+f"(d[2]), "+f"(d[3])
        : "r"(a[0]), "r"(a[1]), "r"(a[2]), "r"(a[3]), "r"(b0), "r"(b1));
}
__device__ __forceinline__ void ldsm4(uint32_t* r, uint32_t addr) {
    asm volatile("ldmatrix.sync.aligned.m8n8.x4.shared.b16 {%0,%1,%2,%3}, [%4];"
                 : "=r"(r[0]), "=r"(r[1]), "=r"(r[2]), "=r"(r[3]) : "r"(addr));
}
__device__ __forceinline__ void ldsm4t(uint32_t* r, uint32_t addr) {
    asm volatile("ldmatrix.sync.aligned.m8n8.x4.trans.shared.b16 {%0,%1,%2,%3}, [%4];"
                 : "=r"(r[0]), "=r"(r[1]), "=r"(r[2]), "=r"(r[3]) : "r"(addr));
}
__device__ __forceinline__ uint32_t smem_u32(const void* p) {
    uint32_t a;
    asm("{ .reg .u64 t; cvta.to.shared.u64 t, %1; cvt.u32.u64 %0, t; }"
        : "=r"(a) : "l"(p));
    return a;
}

#define CP16(dst, src) \
    asm volatile("cp.async.cg.shared.global [%0], [%1], 16;" \
                 :: "r"(dst), "l"(src) : "memory")
#define CPCOMMIT() asm volatile("cp.async.commit_group;" ::: "memory")
#define CPWAIT(n)  asm volatile("cp.async.wait_group %0;" :: "n"(n) : "memory")

// Half-unit swizzled layouts. Chunk = 8 halves (16B); chunk idx XOR (row&7).
__device__ __forceinline__ int swzh(int r, int rowlen, int c8) {
    return r * rowlen + ((c8 ^ (r & 7)) << 3);
}

// ---------------------------------------------------------------------------
// Kernel -1: x fp32 -> fp16
// ---------------------------------------------------------------------------
__global__ __launch_bounds__(256) void convert_x(const float* __restrict__ x) {
    const int i = (blockIdx.x * 256 + threadIdx.x) * 4;
    float4 v = *(const float4*)&x[i];
    *(__half2*)&g_Xh[i]     = __floats2half2_rn(v.x, v.y);
    *(__half2*)&g_Xh[i + 2] = __floats2half2_rn(v.z, v.w);
}

// ---------------------------------------------------------------------------
// Kernel 0: transpose W [C,H] -> g_Wt [w][H][C] fp16
// ---------------------------------------------------------------------------
__global__ void transpose_w(const float* __restrict__ Wq,
                            const float* __restrict__ Wk,
                            const float* __restrict__ Wv) {
    __shared__ float tile[32][33];
    const int w = blockIdx.z;
    const float* __restrict__ W = (w == 0) ? Wq : (w == 1) ? Wk : Wv;
    const int k0 = blockIdx.x * 32, n0 = blockIdx.y * 32;
    const int tx = threadIdx.x, ty = threadIdx.y;  // 32 x 8
#pragma unroll
    for (int i = 0; i < 32; i += 8)
        tile[ty + i][tx] = W[(k0 + ty + i) * H_ + n0 + tx];
    __syncthreads();
#pragma unroll
    for (int i = 0; i < 32; i += 8)
        g_Wt[w * H_ * C_ + (n0 + ty + i) * C_ + k0 + tx] =
            __float2half_rn(tile[tx][ty + i]);
}

// ---------------------------------------------------------------------------
// Kernel 1: fused QKV projection, FP16 m16n8k16 + ldmatrix + 3-stage cp.async.
// CTA 64(M) x 384(N), grid 128. 8 warps 2M x 4N, warp tile 32x96.
// Stage (halves): A[64][64] (4096) | B[384][64] (24576) = 28672 h = 56KB;
// 3 stages = 168KB -> 1 CTA/SM. K-stages: 16.
// ---------------------------------------------------------------------------
#define PJ_STG 28672                    // halves per stage
#define PJ_SMEM (3 * PJ_STG * 2)        // 172032 B

__global__ __launch_bounds__(256, 1) void proj_mma()
{
    extern __shared__ __half smh[];
    const uint32_t sbase = smem_u32(smh);
    const int tid = threadIdx.x, wid = tid >> 5, lane = tid & 31;
    const int g = lane >> 2, tig = lane & 3;
    const int wm = (wid & 1) << 5;
    const int wn = (wid >> 1) * 96;
    const int m0 = blockIdx.x * 64;

    // staging: A 2 chunks/thread, B 12 chunks/thread (16B chunks)
    const int ar = tid >> 2, ac = (tid & 3) << 1;      // A: row, chunk base
    const __half* srcA = g_Xh + (m0 + ar) * C_ + ac * 8;
    const __half* srcB = g_Wt + ar * C_ + ac * 8;      // rows +64*i

    // ldmatrix bases
    const int arow = wm + (lane & 15);
    const int brow = wn + (lane & 7) + ((lane >> 4) << 3);
    const int bksel = (lane >> 3) & 1;

    float acc[2][12][4];
#pragma unroll
    for (int mt = 0; mt < 2; mt++)
#pragma unroll
        for (int nt = 0; nt < 12; nt++)
#pragma unroll
            for (int i = 0; i < 4; i++) acc[mt][nt][i] = 0.f;

#pragma unroll
    for (int s = 0; s < 2; s++) {
        const uint32_t st = sbase + (uint32_t)(s * PJ_STG) * 2;
        const int k0 = s * 64;
#pragma unroll
        for (int i = 0; i < 2; i++)
            CP16(st + (uint32_t)swzh(ar, 64, ac + i) * 2, srcA + k0 + i * 8);
#pragma unroll
        for (int i = 0; i < 6; i++) {
            int r = ar + i * 64;
#pragma unroll
            for (int j = 0; j < 2; j++)
                CP16(st + (uint32_t)(4096 + swzh(r, 64, ac + j)) * 2,
                     srcB + i * 64 * C_ + k0 + j * 8);
        }
        CPCOMMIT();
    }

    for (int s = 0; s < 16; s++) {
        CPWAIT(1);
        __syncthreads();
        const uint32_t st = sbase + (uint32_t)((s % 3) * PJ_STG) * 2;
#pragma unroll
        for (int kk = 0; kk < 64; kk += 16) {
            uint32_t a[2][4];
#pragma unroll
            for (int mt = 0; mt < 2; mt++)
                ldsm4(a[mt], st + (uint32_t)swzh(arow + mt * 16, 64,
                                                (kk >> 3) + (lane >> 4)) * 2);
#pragma unroll
            for (int p = 0; p < 6; p++) {
                uint32_t b[4];
                ldsm4(b, st + (uint32_t)(4096 + swzh(brow + p * 16, 64,
                                                    (kk >> 3) + bksel)) * 2);
                mma_f16(acc[0][2 * p],     a[0], b[0], b[1]);
                mma_f16(acc[1][2 * p],     a[1], b[0], b[1]);
                mma_f16(acc[0][2 * p + 1], a[0], b[2], b[3]);
                mma_f16(acc[1][2 * p + 1], a[1], b[2], b[3]);
            }
        }
        if (s + 2 < 16) {
            const uint32_t stn = sbase + (uint32_t)(((s + 2) % 3) * PJ_STG) * 2;
            const int k0 = (s + 2) * 64;
#pragma unroll
            for (int i = 0; i < 2; i++)
                CP16(stn + (uint32_t)swzh(ar, 64, ac + i) * 2, srcA + k0 + i * 8);
#pragma unroll
            for (int i = 0; i < 6; i++) {
                int r = ar + i * 64;
#pragma unroll
                for (int j = 0; j < 2; j++)
                    CP16(stn + (uint32_t)(4096 + swzh(r, 64, ac + j)) * 2,
                         srcB + i * 64 * C_ + k0 + j * 8);
            }
        }
        CPCOMMIT();
    }

    // epilogue: fp16 stores to Q/K/V
#pragma unroll
    for (int mt = 0; mt < 2; mt++)
#pragma unroll
        for (int nt = 0; nt < 12; nt++) {
            int n = wn + nt * 8 + tig * 2;
            __half* outp = (n < 128) ? g_Q : (n < 256) ? g_K : g_V;
            int col = n & 127;
            int r = m0 + wm + mt * 16 + g;
            *(__half2*)&outp[r * H_ + col] =
                __floats2half2_rn(acc[mt][nt][0], acc[mt][nt][1]);
            *(__half2*)&outp[(r + 8) * H_ + col] =
                __floats2half2_rn(acc[mt][nt][2], acc[mt][nt][3]);
        }
}

// ---------------------------------------------------------------------------
// Kernel 2: attention partial (split-K flash, chunk=4, 576 units, heavy-first),
// FP16 m16n8k16, in-register softmax, V B-frags via ldmatrix.trans.
// smem (halves): Q[64][128] 8192 | K 8192 | V 8192 | P[64][64] 4096 = 28672 h
// + 256 f stats = 58368 B -> 2 CTAs/SM.
// ---------------------------------------------------------------------------
#define AQ_  0
#define AK_  8192
#define AV_  16384
#define AP_  24576
#define AST_ 28672   // half offset of float stats
#define ATTN_SMEM (28672 * 2 + 256 * 4)   // 58368 B

__global__ __launch_bounds__(256, 2) void attn_part() {
    extern __shared__ __half smh[];
    __half* smP = smh + AP_;
    float* smS = (float*)(smh + AST_);   // [row][4]: max h0,h1, sum h0,h1
    const uint32_t sbase = smem_u32(smh);

    // heavy-first: reverse unit order (high qt first)
    const int idx = (NUNITS - 1) - blockIdx.x;
    const int b = idx / UPB;
    const int u = idx % UPB;
    int a = (int)((sqrtf(2.f * u + 1.f) - 1.f) * 0.5f);
    if (2 * (a + 1) * (a + 2) <= u) a++;
    if (2 * a * (a + 1) > u) a--;
    const int rem = u - 2 * a * (a + 1);
    const int qt = 4 * a + rem / (a + 1);
    const int ch = rem - (rem / (a + 1)) * (a + 1);
    const int m0 = qt * 64;
    const int t0 = ch * 4;
    const int t1 = min(t0 + 4, qt + 1);

    const __half* __restrict__ Qg = g_Q + (b * T_ + m0) * H_;
    const __half* __restrict__ Kg = g_K + b * T_ * H_;
    const __half* __restrict__ Vg = g_V + b * T_ * H_;

    const int tid = threadIdx.x;
    const int wid = tid >> 5, lane = tid & 31;
    const int g = lane >> 2, tig = lane & 3;
    const int wm   = (wid & 3) << 4;
    const int wns  = (wid >> 2) << 5;
    const int wno  = (wid >> 2) << 6;
    const int half_ = wid >> 2;
    const int rA = wm + g, rB = wm + g + 8;

    // ldmatrix bases
    const int arow = wm + (lane & 15);
    const int brow = wns + (lane & 7) + ((lane >> 4) << 3);
    const int bksel = (lane >> 3) & 1;
    const int vrow16 = lane & 15;          // V trans: row = kk + vrow16
    const int vnsel = lane >> 4;           // V trans: n-chunk + vnsel

    // cp staging: 4 chunks/thread per 64x128h tile
    const int crow = tid >> 2, cc = (tid & 3) << 2;

    // prologue: async Q, async K(t0)
#pragma unroll
    for (int i = 0; i < 4; i++)
        CP16(sbase + (uint32_t)(AQ_ + swzh(crow, 128, cc + i)) * 2,
             Qg + crow * H_ + (cc + i) * 8);
    CPCOMMIT();
#pragma unroll
    for (int i = 0; i < 4; i++)
        CP16(sbase + (uint32_t)(AK_ + swzh(crow, 128, cc + i)) * 2,
             Kg + (t0 * 64 + crow) * H_ + (cc + i) * 8);
    CPCOMMIT();

    float m_run2[2] = {-1e30f, -1e30f};
    float l_run2[2] = {0.f, 0.f};
    float oacc[8][4];
#pragma unroll
    for (int nt = 0; nt < 8; nt++)
#pragma unroll
        for (int i = 0; i < 4; i++) oacc[nt][i] = 0.f;

    const float inv_scale = 0.03125f;  // C^-0.5

    for (int t = t0; t < t1; t++) {
        __syncthreads();   // PV(t-1) done -> V buffer + P free
#pragma unroll
        for (int i = 0; i < 4; i++)
            CP16(sbase + (uint32_t)(AV_ + swzh(crow, 128, cc + i)) * 2,
                 Vg + (t * 64 + crow) * H_ + (cc + i) * 8);
        CPCOMMIT();
        CPWAIT(1);         // K(t) (and Q) arrived
        __syncthreads();

        // S = Q @ K^T  (warp 16x32), K=128 in 8 k16 steps
        float sacc[4][4];
#pragma unroll
        for (int nt = 0; nt < 4; nt++)
#pragma unroll
            for (int i = 0; i < 4; i++) sacc[nt][i] = 0.f;

#pragma unroll
        for (int kk = 0; kk < 128; kk += 16) {
            uint32_t aa[4];
            ldsm4(aa, sbase + (uint32_t)(AQ_ + swzh(arow, 128,
                                                    (kk >> 3) + (lane >> 4))) * 2);
#pragma unroll
            for (int p = 0; p < 2; p++) {
                uint32_t bb[4];
                ldsm4(bb, sbase + (uint32_t)(AK_ + swzh(brow + p * 16, 128,
                                                        (kk >> 3) + bksel)) * 2);
                mma_f16(sacc[2 * p],     aa, bb[0], bb[1]);
                mma_f16(sacc[2 * p + 1], aa, bb[2], bb[3]);
            }
        }

        // scale + causal mask in fragment layout
        const bool diag = (t == qt);
#pragma unroll
        for (int nt = 0; nt < 4; nt++) {
            int cn = wns + nt * 8 + tig * 2;
            sacc[nt][0] *= inv_scale;
            sacc[nt][1] *= inv_scale;
            sacc[nt][2] *= inv_scale;
            sacc[nt][3] *= inv_scale;
            if (diag) {
                if (cn > rA)     sacc[nt][0] = -1e30f;
                if (cn + 1 > rA) sacc[nt][1] = -1e30f;
                if (cn > rB)     sacc[nt][2] = -1e30f;
                if (cn + 1 > rB) sacc[nt][3] = -1e30f;
            }
        }

        // row max: quad shfl, then cross-half via smem stats
        float pmaxA = -1e30f, pmaxB = -1e30f;
#pragma unroll
        for (int nt = 0; nt < 4; nt++) {
            pmaxA = fmaxf(pmaxA, fmaxf(sacc[nt][0], sacc[nt][1]));
            pmaxB = fmaxf(pmaxB, fmaxf(sacc[nt][2], sacc[nt][3]));
        }
        pmaxA = fmaxf(pmaxA, __shfl_xor_sync(0xffffffffu, pmaxA, 1));
        pmaxA = fmaxf(pmaxA, __shfl_xor_sync(0xffffffffu, pmaxA, 2));
        pmaxB = fmaxf(pmaxB, __shfl_xor_sync(0xffffffffu, pmaxB, 1));
        pmaxB = fmaxf(pmaxB, __shfl_xor_sync(0xffffffffu, pmaxB, 2));
        if (tig == 0) {
            smS[rA * 4 + half_] = pmaxA;
            smS[rB * 4 + half_] = pmaxB;
        }
        __syncthreads();   // stats visible + all warps done reading smK

        if (t + 1 < t1) {  // prefetch K(t+1), overlaps softmax + PV
#pragma unroll
            for (int i = 0; i < 4; i++)
                CP16(sbase + (uint32_t)(AK_ + swzh(crow, 128, cc + i)) * 2,
                     Kg + ((t + 1) * 64 + crow) * H_ + (cc + i) * 8);
        }
        CPCOMMIT();

        float mxA = fmaxf(pmaxA, smS[rA * 4 + (1 - half_)]);
        float mxB = fmaxf(pmaxB, smS[rB * 4 + (1 - half_)]);
        float mnewA = fmaxf(m_run2[0], mxA);
        float mnewB = fmaxf(m_run2[1], mxB);
        float corrA = __expf(m_run2[0] - mnewA);
        float corrB = __expf(m_run2[1] - mnewB);
        m_run2[0] = mnewA; m_run2[1] = mnewB;

        float psumA = 0.f, psumB = 0.f;
#pragma unroll
        for (int nt = 0; nt < 4; nt++) {
            int cn = wns + nt * 8 + tig * 2;
            float p0 = __expf(sacc[nt][0] - mnewA);
            float p1 = __expf(sacc[nt][1] - mnewA);
            float p2 = __expf(sacc[nt][2] - mnewB);
            float p3 = __expf(sacc[nt][3] - mnewB);
            psumA += p0 + p1;
            psumB += p2 + p3;
            *(__half2*)&smP[swzh(rA, 64, cn >> 3) + (cn & 7)] =
                __floats2half2_rn(p0, p1);
            *(__half2*)&smP[swzh(rB, 64, cn >> 3) + (cn & 7)] =
                __floats2half2_rn(p2, p3);
        }
        psumA += __shfl_xor_sync(0xffffffffu, psumA, 1);
        psumA += __shfl_xor_sync(0xffffffffu, psumA, 2);
        psumB += __shfl_xor_sync(0xffffffffu, psumB, 1);
        psumB += __shfl_xor_sync(0xffffffffu, psumB, 2);
        if (tig == 0) {
            smS[rA * 4 + 2 + half_] = psumA;
            smS[rB * 4 + 2 + half_] = psumB;
        }
        if (t + 1 < t1) { CPWAIT(1); } else { CPWAIT(0); }  // V(t) arrived
        __syncthreads();

        l_run2[0] = l_run2[0] * corrA + psumA + smS[rA * 4 + 2 + (1 - half_)];
        l_run2[1] = l_run2[1] * corrB + psumB + smS[rB * 4 + 2 + (1 - half_)];

        // rescale O, then O += P @ V (warp 16x64), K=64 in 4 k16 steps;
        // V B-frags via ldmatrix.trans on [s][h] tiles.
#pragma unroll
        for (int nt = 0; nt < 8; nt++) {
            oacc[nt][0] *= corrA; oacc[nt][1] *= corrA;
            oacc[nt][2] *= corrB; oacc[nt][3] *= corrB;
        }
#pragma unroll
        for (int kk = 0; kk < 64; kk += 16) {
            uint32_t aa[4];
            ldsm4(aa, sbase + (uint32_t)(AP_ + swzh(arow, 64,
                                                    (kk >> 3) + (lane >> 4))) * 2);
#pragma unroll
            for (int p = 0; p < 4; p++) {
                uint32_t bb[4];
                int vr = kk + vrow16;
                ldsm4t(bb, sbase + (uint32_t)(AV_ + swzh(vr, 128,
                                        (wno >> 3) + p * 2 + vnsel)) * 2);
                mma_f16(oacc[2 * p],     aa, bb[0], bb[1]);
                mma_f16(oacc[2 * p + 1], aa, bb[2], bb[3]);
            }
        }
    }

    // write unnormalized partials + per-row (m, l)
    const int p = idx;
    if (tig == 0 && half_ == 0) {
        g_ml[(p * 64 + rA) * 2 + 0] = m_run2[0];
        g_ml[(p * 64 + rA) * 2 + 1] = l_run2[0];
        g_ml[(p * 64 + rB) * 2 + 0] = m_run2[1];
        g_ml[(p * 64 + rB) * 2 + 1] = l_run2[1];
    }
#pragma unroll
    for (int nt = 0; nt < 8; nt++) {
        int cc2 = wno + nt * 8 + tig * 2;
        *(float2*)&g_Opart[(p * 64 + rA) * H_ + cc2] =
            make_float2(oacc[nt][0], oacc[nt][1]);
        *(float2*)&g_Opart[(p * 64 + rB) * H_ + cc2] =
            make_float2(oacc[nt][2], oacc[nt][3]);
    }
}

// ---------------------------------------------------------------------------
// Kernel 3: merge partials -> final out.  One float4 per thread (1024 CTAs).
// ---------------------------------------------------------------------------
__global__ __launch_bounds__(256) void attn_merge(float* __restrict__ out) {
    const int gidx = blockIdx.x * 256 + threadIdx.x;
    const int row = gidx >> 5;           // 0..8191
    const int c0 = (gidx & 31) << 2;     // float4 col
    const int b = row >> 11, rr = row & 2047;
    const int qt = rr >> 6, r = rr & 63;
    const int a = qt >> 2, rm = qt & 3;
    const int nch = a + 1;
    const int ubase = (a + 1) * (2 * a + rm);
    const int pbase = b * UPB + ubase;

    float m = -1e30f;
#pragma unroll 8
    for (int c = 0; c < nch; c++)
        m = fmaxf(m, g_ml[((pbase + c) * 64 + r) * 2]);
    float l = 0.f;
    float ax = 0.f, ay = 0.f, az = 0.f, aw = 0.f;
#pragma unroll 8
    for (int c = 0; c < nch; c++) {
        float wgt = __expf(g_ml[((pbase + c) * 64 + r) * 2] - m);
        l += wgt * g_ml[((pbase + c) * 64 + r) * 2 + 1];
        float4 v = *(const float4*)&g_Opart[((pbase + c) * 64 + r) * H_ + c0];
        ax += wgt * v.x; ay += wgt * v.y; az += wgt * v.z; aw += wgt * v.w;
    }
    const float invl = 1.f / l;
    *(float4*)&out[row * H_ + c0] =
        make_float4(ax * invl, ay * invl, az * invl, aw * invl);
}

// ---------------------------------------------------------------------------
// Launch
// ---------------------------------------------------------------------------
extern "C" void kernel_launch(void* const* d_in, const int* in_sizes, int n_in,
                              void* d_out, int out_size) {
    const float* x  = (const float*)d_in[0];
    const float* Wq = (const float*)d_in[1];
    const float* Wk = (const float*)d_in[2];
    const float* Wv = (const float*)d_in[3];
    // d_in[4] = mask: tril by construction -> causal logic used directly.
    float* out = (float*)d_out;

    convert_x<<<BT_ * C_ / 4 / 256, 256>>>(x);

    dim3 gt(C_ / 32, H_ / 32, 3);
    transpose_w<<<gt, dim3(32, 8)>>>(Wq, Wk, Wv);

    cudaFuncSetAttribute((const void*)proj_mma,
                         cudaFuncAttributeMaxDynamicSharedMemorySize, PJ_SMEM);
    proj_mma<<<BT_ / 64, 256, PJ_SMEM>>>();

    cudaFuncSetAttribute((const void*)attn_part,
                         cudaFuncAttributeMaxDynamicSharedMemorySize, ATTN_SMEM);
    attn_part<<<NUNITS, 256, ATTN_SMEM>>>();

    attn_merge<<<BT_ * H_ / 4 / 256, 256>>>(out);
}